// round 8
// baseline (speedup 1.0000x reference)
#include <cuda_runtime.h>
#include <math_constants.h>

#define T_LEN 8192
#define B_SZ  256
#define E_CH  8
#define KS    15
#define TD    1024
#define TPI_F 6.28318530717958647692f

#define PAD(i)   ((i) + ((i) >> 5))
#define F2PAD(i) ((i) + ((i) >> 4))

typedef unsigned long long ull;

// ---- packed f32x2 helpers ----
__device__ __forceinline__ ull pk2(float lo, float hi) {
    ull r;
    asm("mov.b64 %0, {%1, %2};" : "=l"(r) : "f"(lo), "f"(hi));
    return r;
}
__device__ __forceinline__ float2 unpk2(ull v) {
    float lo, hi;
    asm("mov.b64 {%0, %1}, %2;" : "=f"(lo), "=f"(hi) : "l"(v));
    return make_float2(lo, hi);
}
__device__ __forceinline__ ull fma2(ull a, ull b, ull c) {
    ull d;
    asm("fma.rn.f32x2 %0, %1, %2, %3;" : "=l"(d) : "l"(a), "l"(b), "l"(c));
    return d;
}
__device__ __forceinline__ ull add2(ull a, ull b) {
    ull d;
    asm("add.rn.f32x2 %0, %1, %2;" : "=l"(d) : "l"(a), "l"(b));
    return d;
}

__device__ __forceinline__ float2 cmulf(float2 a, float2 b) {
    return make_float2(a.x * b.x - a.y * b.y, a.x * b.y + a.y * b.x);
}
__device__ __forceinline__ float2 cadd(float2 a, float2 b) {
    return make_float2(a.x + b.x, a.y + b.y);
}
__device__ __forceinline__ float2 csub(float2 a, float2 b) {
    return make_float2(a.x - b.x, a.y - b.y);
}

// compensated float-float accumulation (TwoSum based)
__device__ __forceinline__ float2 df_add(float2 a, float2 b) {
    float s = a.x + b.x;
    float v = s - a.x;
    float e = (a.x - (s - v)) + (b.x - v);
    e = e + a.y + b.y;
    float hi = s + e;
    return make_float2(hi, e - (hi - s));
}
__device__ __forceinline__ float2 df_addf(float2 a, float b) {
    return df_add(a, make_float2(b, 0.f));
}

// ---------------------------------------------------------------------------
// Kernel A: fused per-channel dilated conv pair -> latent (B,E,T)
// Coset-blocked register streaming + packed f32x2 math. (R5 proven body.)
// ---------------------------------------------------------------------------
__global__ __launch_bounds__(256, 2) void latent_kernel(
    const float* __restrict__ x,
    const float* __restrict__ W1, const float* __restrict__ b1,
    const float* __restrict__ W2, const float* __restrict__ b2,
    float* __restrict__ latent)
{
    extern __shared__ float sm[];
    float* sx  = sm;                               // PAD(8192) -> 8448 floats
    ull*   shp = (ull*)(sm + 8448);                // F2PAD(8192) -> 8704 ull

    const int be = blockIdx.x;
    const int e  = be & 7;
    const int b  = be >> 3;
    const int d  = 1 << e;
    const int tid = threadIdx.x;

    const float* xrow = x + (size_t)b * T_LEN;
    for (int i = tid; i < T_LEN; i += 256) sx[PAD(i)] = xrow[i];

    ull w1pk[KS];
#pragma unroll
    for (int j = 0; j < KS; j++)
        w1pk[j] = pk2(W1[e * 30 + j], W1[e * 30 + 15 + j]);
    const ull bias1 = pk2(b1[2 * e], b1[2 * e + 1]);
    __syncthreads();

    // ---- stage 1: packed h = (h0,h1)
#pragma unroll 1
    for (int it = 0; it < 4; it++) {
        const int cc = it * 256 + tid;
        const int p  = cc & (d - 1);
        const int qc = cc >> e;
        const int tb = p + (qc << (e + 3));
        ull xd[22];
#pragma unroll
        for (int m = 0; m < 22; m++) {
            int idx = tb + (m - 7) * d;
            float v = ((unsigned)idx < (unsigned)T_LEN) ? sx[PAD(idx)] : 0.f;
            xd[m] = pk2(v, v);
        }
#pragma unroll
        for (int rr = 0; rr < 8; rr++) {
            ull a0 = bias1, a1 = 0ULL;
#pragma unroll
            for (int j = 0; j < KS; j += 2) a0 = fma2(w1pk[j], xd[rr + j], a0);
#pragma unroll
            for (int j = 1; j < KS; j += 2) a1 = fma2(w1pk[j], xd[rr + j], a1);
            shp[F2PAD(tb + rr * d)] = add2(a0, a1);
        }
    }

    ull w2pk[KS];
#pragma unroll
    for (int k = 0; k < KS; k++)
        w2pk[k] = pk2(W2[e * 30 + k], W2[e * 30 + 15 + k]);
    const ull bias2 = pk2(b2[e], 0.f);
    __syncthreads();

    // ---- stage 2: packed dot over (h0,h1), results staged into sx
#pragma unroll 1
    for (int it = 0; it < 4; it++) {
        const int cc = it * 256 + tid;
        const int p  = cc & (d - 1);
        const int qc = cc >> e;
        const int tb = p + (qc << (e + 3));
        ull gp[22];
#pragma unroll
        for (int m = 0; m < 22; m++) {
            int idx = tb + (m - 7) * d;
            gp[m] = ((unsigned)idx < (unsigned)T_LEN) ? shp[F2PAD(idx)] : 0ULL;
        }
#pragma unroll
        for (int rr = 0; rr < 8; rr++) {
            ull a0 = bias2, a1 = 0ULL;
#pragma unroll
            for (int k = 0; k < KS; k += 2) a0 = fma2(w2pk[k], gp[rr + k], a0);
#pragma unroll
            for (int k = 1; k < KS; k += 2) a1 = fma2(w2pk[k], gp[rr + k], a1);
            float2 r = unpk2(add2(a0, a1));
            sx[PAD(tb + rr * d)] = r.x + r.y;
        }
    }
    __syncthreads();

    float* lrow = latent + (size_t)be * T_LEN;
    for (int i = tid; i < T_LEN; i += 256) lrow[i] = sx[PAD(i)];
}

// ---------------------------------------------------------------------------
// Kernel B: per-(b,e) row — fc dots, real FFT (8192 real via complex 4096),
// radix-8 Stockham (4 stages, 512 threads). Twiddle powers via squaring tree
// (dep depth 4 instead of 7). Compensated fp32 reductions.
// ---------------------------------------------------------------------------
__global__ __launch_bounds__(512, 2) void fft_kernel(
    const float* __restrict__ latent,
    const float* __restrict__ fcW, const float* __restrict__ fcb,
    float* __restrict__ pOut, float* __restrict__ fOut,
    float* __restrict__ aOut, float* __restrict__ bOut)
{
    const int M = 4096;
    extern __shared__ float smf[];
    float2* bufA = (float2*)smf;         // F2PAD -> 4352 slots
    float2* bufB = bufA + 4352;
    float2* tw   = bufB + 4352;          // 512 twiddles
    __shared__ float2 red2[64];

    const int be = blockIdx.x;
    const int e  = be & 7;
    const int tid = threadIdx.x;

    const float2* rowc = (const float2*)(latent + (size_t)be * T_LEN);
    const float2* fw0  = (const float2*)(fcW + (size_t)(e * 2 + 0) * T_LEN);
    const float2* fw1  = (const float2*)(fcW + (size_t)(e * 2 + 1) * T_LEN);

    float2 v0 = make_float2(0.f, 0.f), v1 = make_float2(0.f, 0.f);
#pragma unroll
    for (int i = tid; i < M; i += 512) {
        float2 z = rowc[i];
        bufA[F2PAD(i)] = z;
        float2 a0 = fw0[i], a1 = fw1[i];
        v0 = df_addf(v0, z.x * a0.x + z.y * a0.y);
        v1 = df_addf(v1, z.x * a1.x + z.y * a1.y);
    }
    {
        float s, c;
        sincosf(-(float)CUDART_PI * (float)tid / 2048.0f, &s, &c);
        tw[tid] = make_float2(c, s);
    }
    __syncthreads();

    const float RS = 0.70710678118654752440f;
    float2* bin  = bufA;
    float2* bout = bufB;
#pragma unroll
    for (int sg = 0; sg < 4; sg++) {
        const int m = 1 << (3 * sg);
        const int idx = tid;
        const int r = idx & (m - 1);
        float2 W = tw[r << (9 - 3 * sg)];

        float2 u0 = bin[F2PAD(idx)];
        float2 z1 = bin[F2PAD(idx + 512)];
        float2 z2 = bin[F2PAD(idx + 1024)];
        float2 z3 = bin[F2PAD(idx + 1536)];
        float2 z4 = bin[F2PAD(idx + 2048)];
        float2 z5 = bin[F2PAD(idx + 2560)];
        float2 z6 = bin[F2PAD(idx + 3072)];
        float2 z7 = bin[F2PAD(idx + 3584)];

        // twiddle power squaring tree: depth 4
        float2 W2 = cmulf(W, W);
        float2 W3 = cmulf(W2, W);
        float2 W4 = cmulf(W2, W2);
        float2 W5 = cmulf(W4, W);
        float2 W6 = cmulf(W4, W2);
        float2 W7 = cmulf(W4, W3);

        float2 u1 = cmulf(z1, W);
        float2 u2 = cmulf(z2, W2);
        float2 u3 = cmulf(z3, W3);
        float2 u4 = cmulf(z4, W4);
        float2 u5 = cmulf(z5, W5);
        float2 u6 = cmulf(z6, W6);
        float2 u7 = cmulf(z7, W7);

        float2 t0 = cadd(u0, u4), t1 = csub(u0, u4);
        float2 t2 = cadd(u2, u6), t3 = csub(u2, u6);
        float2 E0 = cadd(t0, t2);
        float2 E1 = make_float2(t1.x + t3.y, t1.y - t3.x);
        float2 E2 = csub(t0, t2);
        float2 E3 = make_float2(t1.x - t3.y, t1.y + t3.x);
        float2 s0 = cadd(u1, u5), s1 = csub(u1, u5);
        float2 s2 = cadd(u3, u7), s3 = csub(u3, u7);
        float2 O0 = cadd(s0, s2);
        float2 O1 = make_float2(s1.x + s3.y, s1.y - s3.x);
        float2 O2 = csub(s0, s2);
        float2 O3 = make_float2(s1.x - s3.y, s1.y + s3.x);
        float2 Q1 = make_float2(RS * (O1.x + O1.y), RS * (O1.y - O1.x));
        float2 Q2 = make_float2(O2.y, -O2.x);
        float2 Q3 = make_float2(RS * (O3.y - O3.x), -RS * (O3.x + O3.y));

        const int ob = ((idx - r) << 3) + r;
        bout[F2PAD(ob)]         = cadd(E0, O0);
        bout[F2PAD(ob + m)]     = cadd(E1, Q1);
        bout[F2PAD(ob + 2 * m)] = cadd(E2, Q2);
        bout[F2PAD(ob + 3 * m)] = cadd(E3, Q3);
        bout[F2PAD(ob + 4 * m)] = csub(E0, O0);
        bout[F2PAD(ob + 5 * m)] = csub(E1, Q1);
        bout[F2PAD(ob + 6 * m)] = csub(E2, Q2);
        bout[F2PAD(ob + 7 * m)] = csub(E3, Q3);
        __syncthreads();
        float2* tmp = bin; bin = bout; bout = tmp;
    }

    float2 psum = make_float2(0.f, 0.f), wsum = make_float2(0.f, 0.f);
#pragma unroll
    for (int k0 = 0; k0 < 8; k0++) {
        int k = tid + 1 + k0 * 512;
        if (k < M) {
            float2 zk = bin[F2PAD(k)];
            float2 zm = bin[F2PAD(M - k)];
            float Ax = 0.5f * (zk.x + zm.x), Ay = 0.5f * (zk.y - zm.y);
            float Bx = 0.5f * (zk.x - zm.x), By = 0.5f * (zk.y + zm.y);
            float s, c;
            __sincosf(-(float)CUDART_PI * (float)k / (float)M, &s, &c);
            float Xr = Ax + c * By + s * Bx;
            float Xi = Ay - c * Bx + s * By;
            float pw = Xr * Xr + Xi * Xi;
            psum = df_addf(psum, pw);
            wsum = df_addf(wsum, (float)k * pw);
        }
    }
    if (tid == 0) {
        float xm = bin[0].x - bin[0].y;
        psum = df_addf(psum, xm * xm);
        wsum = df_addf(wsum, (float)M * (xm * xm));
    }

    const unsigned mask = 0xffffffffu;
#pragma unroll
    for (int o = 16; o > 0; o >>= 1) {
        psum = df_add(psum, make_float2(__shfl_down_sync(mask, psum.x, o),
                                        __shfl_down_sync(mask, psum.y, o)));
        wsum = df_add(wsum, make_float2(__shfl_down_sync(mask, wsum.x, o),
                                        __shfl_down_sync(mask, wsum.y, o)));
        v0   = df_add(v0,   make_float2(__shfl_down_sync(mask, v0.x, o),
                                        __shfl_down_sync(mask, v0.y, o)));
        v1   = df_add(v1,   make_float2(__shfl_down_sync(mask, v1.x, o),
                                        __shfl_down_sync(mask, v1.y, o)));
    }
    const int warp = tid >> 5, lane = tid & 31;
    if (lane == 0) {
        red2[warp] = psum; red2[16 + warp] = wsum;
        red2[32 + warp] = v0; red2[48 + warp] = v1;
    }
    __syncthreads();
    if (tid == 0) {
        double P = 0, Wm = 0, V0 = 0, V1 = 0;
        for (int i = 0; i < 16; i++) {
            P  += (double)red2[i].x      + (double)red2[i].y;
            Wm += (double)red2[16 + i].x + (double)red2[16 + i].y;
            V0 += (double)red2[32 + i].x + (double)red2[32 + i].y;
            V1 += (double)red2[48 + i].x + (double)red2[48 + i].y;
        }
        V0 += (double)fcb[e * 2];
        V1 += (double)fcb[e * 2 + 1];
        float f    = (float)(0.5 * Wm / P);
        float a    = 2.0f * sqrtf((float)P) / (float)T_LEN;
        float boff = (bin[0].x + bin[0].y) / (float)T_LEN;
        float p    = atan2f((float)V1, (float)V0) / TPI_F;
        pOut[be] = p; fOut[be] = f; aOut[be] = a; bOut[be] = boff;
    }
}

// ---------------------------------------------------------------------------
// Kernel D: sinusoid resynthesis via rotation recurrence + fused 3-level
// grouped deconv tree. Levels register-blocked: 8 consecutive outputs per
// thread-chunk, window loaded with LDS.128 (ulonglong2) — ~2.7x less
// effective smem crossbar traffic than per-output loads.
// ---------------------------------------------------------------------------
__global__ __launch_bounds__(256) void sig_tree_kernel(
    const float* __restrict__ pArr, const float* __restrict__ fArr,
    const float* __restrict__ aArr, const float* __restrict__ bArr,
    const float* __restrict__ dW0, const float* __restrict__ db0,
    const float* __restrict__ dW1, const float* __restrict__ db1,
    const float* __restrict__ dW2, const float* __restrict__ db2,
    float* __restrict__ sig, float* __restrict__ outp)
{
    extern __shared__ float smd[];
    const int SW  = TD + 42;   // 1066
    const int W0L = TD + 28;   // 1052
    const int W1L = TD + 14;   // 1038
    float2* ssig2 = (float2*)smd;
    float2* sy0_2 = ssig2 + 4 * SW;
    float2* sy1_2 = sy0_2 + 2 * W0L;
    __shared__ float sca[8], scf[8], scp[8], scb[8];
    __shared__ float2 rotv[8];
    __shared__ ull sdw0p[4 * KS], sdw1p[2 * KS], sdw2p[KS];
    __shared__ float sdb0[4], sdb1[2], sdb2[1];

    const int blk  = blockIdx.x;
    const int tile = blk & 7;
    const int b    = blk >> 3;
    const int t0   = tile * TD;
    const int tid  = threadIdx.x;
    const float inv = 2.0f / (float)(T_LEN - 1);

    if (tid < 8) {
        float fv = fArr[b * 8 + tid];
        sca[tid] = aArr[b * 8 + tid]; scf[tid] = fv;
        scp[tid] = pArr[b * 8 + tid]; scb[tid] = bArr[b * 8 + tid];
        float S, C;
        sincospif(2.0f * fv * inv, &S, &C);
        rotv[tid] = make_float2(C, S);
    }
    if (tid < 4 * KS) {
        int g = tid / KS, k = tid - g * KS;
        sdw0p[tid] = pk2(dW0[(2 * g) * KS + k], dW0[(2 * g + 1) * KS + k]);
    }
    if (tid < 2 * KS) {
        int g = tid / KS, k = tid - g * KS;
        sdw1p[tid] = pk2(dW1[(2 * g) * KS + k], dW1[(2 * g + 1) * KS + k]);
    }
    if (tid < KS) sdw2p[tid] = pk2(dW2[tid], dW2[KS + tid]);
    if (tid < 4) sdb0[tid] = db0[tid];
    if (tid < 2) sdb1[tid] = db1[tid];
    if (tid == 0) sdb2[0] = db2[0];
    __syncthreads();

    // sinusoid generation: 64 threads per pair-row, 17 contiguous elems each
    {
        const int pr  = tid >> 6;
        const int sub = tid & 63;
        const int j0  = sub * 17;
        const int ts  = t0 - 21 + j0;
        const int e0 = 2 * pr, e1 = 2 * pr + 1;
        const float arg0 = -1.0f + (float)ts * inv;
        float s0, c0, s1, c1;
        sincospif(2.0f * (scf[e0] * arg0 + scp[e0]), &s0, &c0);
        sincospif(2.0f * (scf[e1] * arg0 + scp[e1]), &s1, &c1);
        const float2 r0 = rotv[e0], r1 = rotv[e1];
        const float a0 = sca[e0], b0 = scb[e0];
        const float a1 = sca[e1], b1v = scb[e1];
#pragma unroll
        for (int jj = 0; jj < 17; jj++) {
            int j = j0 + jj;
            int t = ts + jj;
            if (j < SW) {
                bool ok = ((unsigned)t < (unsigned)T_LEN);
                float v0 = ok ? (a0 * s0 + b0)  : 0.f;
                float v1 = ok ? (a1 * s1 + b1v) : 0.f;
                ssig2[pr * SW + j] = make_float2(v0, v1);
            }
            float ns0 = s0 * r0.x + c0 * r0.y;
            c0 = c0 * r0.x - s0 * r0.y; s0 = ns0;
            float ns1 = s1 * r1.x + c1 * r1.y;
            c1 = c1 * r1.x - s1 * r1.y; s1 = ns1;
        }
    }
    __syncthreads();

    // coalesced sig writeback
    for (int i = tid; i < 8 * TD; i += 256) {
        int e = i >> 10, jj = i & (TD - 1);
        float2 v = ssig2[(e >> 1) * SW + 21 + jj];
        sig[((size_t)b * 8 + e) * T_LEN + t0 + jj] = (e & 1) ? v.y : v.x;
    }

    // ---- level 0: 4 groups, blocked R=8, LDS.128 window loads
    {
        const int CPG = 132;                 // ceil(W0L/8)
#pragma unroll 1
        for (int chunk = tid; chunk < 4 * CPG; chunk += 256) {
            const int g  = chunk / CPG;
            const int c  = chunk - g * CPG;
            const int j0 = c * 8;
            const ulonglong2* s4 =
                (const ulonglong2*)((const ull*)(ssig2 + g * SW) + j0);
            ull sv[22];
#pragma unroll
            for (int i = 0; i < 11; i++) {
                ulonglong2 v = s4[i];
                sv[2 * i] = v.x; sv[2 * i + 1] = v.y;
            }
            ull wp[KS];
#pragma unroll
            for (int k = 0; k < KS; k++) wp[k] = sdw0p[g * KS + k];
            const ull bg = pk2(sdb0[g], 0.f);
            float* dst = (float*)(sy0_2 + (g >> 1) * W0L);
            const int comp = g & 1;
#pragma unroll
            for (int q = 0; q < 8; q++) {
                const int j = j0 + q;
                if (j < W0L) {
                    ull a0 = bg, a1 = 0ULL;
#pragma unroll
                    for (int k = 0; k < KS; k += 2) a0 = fma2(wp[k], sv[q + k], a0);
#pragma unroll
                    for (int k = 1; k < KS; k += 2) a1 = fma2(wp[k], sv[q + k], a1);
                    float2 r = unpk2(add2(a0, a1));
                    const int t = t0 - 14 + j;
                    dst[2 * j + comp] =
                        ((unsigned)t < (unsigned)T_LEN) ? (r.x + r.y) : 0.f;
                }
            }
        }
    }
    __syncthreads();

    // ---- level 1: 2 groups, blocked R=8
    {
        const int CPG = 130;                 // ceil(W1L/8)
#pragma unroll 1
        for (int chunk = tid; chunk < 2 * CPG; chunk += 256) {
            const int g  = chunk / CPG;
            const int c  = chunk - g * CPG;
            const int j0 = c * 8;
            const ulonglong2* s4 =
                (const ulonglong2*)((const ull*)(sy0_2 + g * W0L) + j0);
            ull sv[22];
#pragma unroll
            for (int i = 0; i < 11; i++) {
                ulonglong2 v = s4[i];
                sv[2 * i] = v.x; sv[2 * i + 1] = v.y;
            }
            ull wp[KS];
#pragma unroll
            for (int k = 0; k < KS; k++) wp[k] = sdw1p[g * KS + k];
            const ull bg = pk2(sdb1[g], 0.f);
            float* dst = (float*)sy1_2;
#pragma unroll
            for (int q = 0; q < 8; q++) {
                const int j = j0 + q;
                if (j < W1L) {
                    ull a0 = bg, a1 = 0ULL;
#pragma unroll
                    for (int k = 0; k < KS; k += 2) a0 = fma2(wp[k], sv[q + k], a0);
#pragma unroll
                    for (int k = 1; k < KS; k += 2) a1 = fma2(wp[k], sv[q + k], a1);
                    float2 r = unpk2(add2(a0, a1));
                    const int t = t0 - 7 + j;
                    dst[2 * j + g] =
                        ((unsigned)t < (unsigned)T_LEN) ? (r.x + r.y) : 0.f;
                }
            }
        }
    }
    __syncthreads();

    // ---- level 2: 1 group, blocked R=8, float4 global stores
    if (tid < 128) {
        const int j0 = tid * 8;
        const ulonglong2* s4 = (const ulonglong2*)((const ull*)sy1_2 + j0);
        ull sv[22];
#pragma unroll
        for (int i = 0; i < 11; i++) {
            ulonglong2 v = s4[i];
            sv[2 * i] = v.x; sv[2 * i + 1] = v.y;
        }
        ull wp[KS];
#pragma unroll
        for (int k = 0; k < KS; k++) wp[k] = sdw2p[k];
        const ull bg = pk2(sdb2[0], 0.f);
        float res[8];
#pragma unroll
        for (int q = 0; q < 8; q++) {
            ull a0 = bg, a1 = 0ULL;
#pragma unroll
            for (int k = 0; k < KS; k += 2) a0 = fma2(wp[k], sv[q + k], a0);
#pragma unroll
            for (int k = 1; k < KS; k += 2) a1 = fma2(wp[k], sv[q + k], a1);
            float2 r = unpk2(add2(a0, a1));
            res[q] = r.x + r.y;
        }
        float4* o4 = (float4*)(outp + (size_t)b * T_LEN + t0 + j0);
        o4[0] = make_float4(res[0], res[1], res[2], res[3]);
        o4[1] = make_float4(res[4], res[5], res[6], res[7]);
    }
}

// ---------------------------------------------------------------------------
extern "C" void kernel_launch(void* const* d_in, const int* in_sizes, int n_in,
                              void* d_out, int out_size)
{
    const float* x   = (const float*)d_in[0];
    const float* W1  = (const float*)d_in[1];
    const float* b1  = (const float*)d_in[2];
    const float* W2  = (const float*)d_in[3];
    const float* b2  = (const float*)d_in[4];
    const float* fcW = (const float*)d_in[5];
    const float* fcb = (const float*)d_in[6];
    const float* dW0 = (const float*)d_in[7];
    const float* db0 = (const float*)d_in[8];
    const float* dW1 = (const float*)d_in[9];
    const float* db1 = (const float*)d_in[10];
    const float* dW2 = (const float*)d_in[11];
    const float* db2 = (const float*)d_in[12];

    float* out = (float*)d_out;
    float* outMain = out;                                        // (B, T)
    float* latent  = out + (size_t)B_SZ * T_LEN;                 // (B, E, T)
    float* sig     = latent + (size_t)B_SZ * E_CH * T_LEN;       // (B, E, T)
    float* pOut    = sig + (size_t)B_SZ * E_CH * T_LEN;          // (B, E, 1)
    float* fOut    = pOut + B_SZ * E_CH;
    float* aOut    = fOut + B_SZ * E_CH;
    float* bOut    = aOut + B_SZ * E_CH;

    const size_t smA = (size_t)8448 * sizeof(float) + (size_t)8704 * sizeof(ull);
    const size_t smB = (size_t)(4352 * 2 + 512) * sizeof(float2);
    const size_t smD = (size_t)(4 * (TD + 42) + 2 * (TD + 28) + (TD + 14)) * sizeof(float2);

    cudaFuncSetAttribute(latent_kernel,   cudaFuncAttributeMaxDynamicSharedMemorySize, (int)smA);
    cudaFuncSetAttribute(fft_kernel,      cudaFuncAttributeMaxDynamicSharedMemorySize, (int)smB);
    cudaFuncSetAttribute(sig_tree_kernel, cudaFuncAttributeMaxDynamicSharedMemorySize, (int)smD);

    latent_kernel<<<B_SZ * E_CH, 256, smA>>>(x, W1, b1, W2, b2, latent);
    fft_kernel<<<B_SZ * E_CH, 512, smB>>>(latent, fcW, fcb, pOut, fOut, aOut, bOut);
    sig_tree_kernel<<<B_SZ * (T_LEN / TD), 256, smD>>>(pOut, fOut, aOut, bOut,
                                                       dW0, db0, dW1, db1, dW2, db2,
                                                       sig, outMain);
}

// round 9
// speedup vs baseline: 1.2123x; 1.2123x over previous
#include <cuda_runtime.h>
#include <math_constants.h>

#define T_LEN 8192
#define B_SZ  256
#define E_CH  8
#define KS    15
#define TD    1024
#define TPI_F 6.28318530717958647692f

#define PAD(i)   ((i) + ((i) >> 5))
#define F2PAD(i) ((i) + ((i) >> 4))

typedef unsigned long long ull;

// ---- packed f32x2 helpers ----
__device__ __forceinline__ ull pk2(float lo, float hi) {
    ull r;
    asm("mov.b64 %0, {%1, %2};" : "=l"(r) : "f"(lo), "f"(hi));
    return r;
}
__device__ __forceinline__ float2 unpk2(ull v) {
    float lo, hi;
    asm("mov.b64 {%0, %1}, %2;" : "=f"(lo), "=f"(hi) : "l"(v));
    return make_float2(lo, hi);
}
__device__ __forceinline__ ull fma2(ull a, ull b, ull c) {
    ull d;
    asm("fma.rn.f32x2 %0, %1, %2, %3;" : "=l"(d) : "l"(a), "l"(b), "l"(c));
    return d;
}
__device__ __forceinline__ ull add2(ull a, ull b) {
    ull d;
    asm("add.rn.f32x2 %0, %1, %2;" : "=l"(d) : "l"(a), "l"(b));
    return d;
}

__device__ __forceinline__ float2 cmulf(float2 a, float2 b) {
    return make_float2(a.x * b.x - a.y * b.y, a.x * b.y + a.y * b.x);
}
__device__ __forceinline__ float2 cadd(float2 a, float2 b) {
    return make_float2(a.x + b.x, a.y + b.y);
}
__device__ __forceinline__ float2 csub(float2 a, float2 b) {
    return make_float2(a.x - b.x, a.y - b.y);
}

// compensated float-float accumulation (TwoSum based)
__device__ __forceinline__ float2 df_add(float2 a, float2 b) {
    float s = a.x + b.x;
    float v = s - a.x;
    float e = (a.x - (s - v)) + (b.x - v);
    e = e + a.y + b.y;
    float hi = s + e;
    return make_float2(hi, e - (hi - s));
}
__device__ __forceinline__ float2 df_addf(float2 a, float b) {
    return df_add(a, make_float2(b, 0.f));
}

// ---------------------------------------------------------------------------
// Kernel A: fused per-channel dilated conv pair -> latent (B,E,T)
// Coset-blocked register streaming + packed f32x2 math. (R5 proven body.)
// ---------------------------------------------------------------------------
__global__ __launch_bounds__(256, 2) void latent_kernel(
    const float* __restrict__ x,
    const float* __restrict__ W1, const float* __restrict__ b1,
    const float* __restrict__ W2, const float* __restrict__ b2,
    float* __restrict__ latent)
{
    extern __shared__ float sm[];
    float* sx  = sm;                               // PAD(8192) -> 8448 floats
    ull*   shp = (ull*)(sm + 8448);                // F2PAD(8192) -> 8704 ull

    const int be = blockIdx.x;
    const int e  = be & 7;
    const int b  = be >> 3;
    const int d  = 1 << e;
    const int tid = threadIdx.x;

    const float* xrow = x + (size_t)b * T_LEN;
    for (int i = tid; i < T_LEN; i += 256) sx[PAD(i)] = xrow[i];

    ull w1pk[KS];
#pragma unroll
    for (int j = 0; j < KS; j++)
        w1pk[j] = pk2(W1[e * 30 + j], W1[e * 30 + 15 + j]);
    const ull bias1 = pk2(b1[2 * e], b1[2 * e + 1]);
    __syncthreads();

#pragma unroll 1
    for (int it = 0; it < 4; it++) {
        const int cc = it * 256 + tid;
        const int p  = cc & (d - 1);
        const int qc = cc >> e;
        const int tb = p + (qc << (e + 3));
        ull xd[22];
#pragma unroll
        for (int m = 0; m < 22; m++) {
            int idx = tb + (m - 7) * d;
            float v = ((unsigned)idx < (unsigned)T_LEN) ? sx[PAD(idx)] : 0.f;
            xd[m] = pk2(v, v);
        }
#pragma unroll
        for (int rr = 0; rr < 8; rr++) {
            ull a0 = bias1, a1 = 0ULL;
#pragma unroll
            for (int j = 0; j < KS; j += 2) a0 = fma2(w1pk[j], xd[rr + j], a0);
#pragma unroll
            for (int j = 1; j < KS; j += 2) a1 = fma2(w1pk[j], xd[rr + j], a1);
            shp[F2PAD(tb + rr * d)] = add2(a0, a1);
        }
    }

    ull w2pk[KS];
#pragma unroll
    for (int k = 0; k < KS; k++)
        w2pk[k] = pk2(W2[e * 30 + k], W2[e * 30 + 15 + k]);
    const ull bias2 = pk2(b2[e], 0.f);
    __syncthreads();

#pragma unroll 1
    for (int it = 0; it < 4; it++) {
        const int cc = it * 256 + tid;
        const int p  = cc & (d - 1);
        const int qc = cc >> e;
        const int tb = p + (qc << (e + 3));
        ull gp[22];
#pragma unroll
        for (int m = 0; m < 22; m++) {
            int idx = tb + (m - 7) * d;
            gp[m] = ((unsigned)idx < (unsigned)T_LEN) ? shp[F2PAD(idx)] : 0ULL;
        }
#pragma unroll
        for (int rr = 0; rr < 8; rr++) {
            ull a0 = bias2, a1 = 0ULL;
#pragma unroll
            for (int k = 0; k < KS; k += 2) a0 = fma2(w2pk[k], gp[rr + k], a0);
#pragma unroll
            for (int k = 1; k < KS; k += 2) a1 = fma2(w2pk[k], gp[rr + k], a1);
            float2 r = unpk2(add2(a0, a1));
            sx[PAD(tb + rr * d)] = r.x + r.y;
        }
    }
    __syncthreads();

    float* lrow = latent + (size_t)be * T_LEN;
    for (int i = tid; i < T_LEN; i += 256) lrow[i] = sx[PAD(i)];
}

// ---------------------------------------------------------------------------
// Kernel B: per-(b,e) row — fc dots, real FFT (8192 real via complex 4096),
// radix-8 Stockham (4 stages, 512 threads), padded smem,
// compensated fp32 reductions. (R5 proven version.)
// ---------------------------------------------------------------------------
__global__ __launch_bounds__(512, 2) void fft_kernel(
    const float* __restrict__ latent,
    const float* __restrict__ fcW, const float* __restrict__ fcb,
    float* __restrict__ pOut, float* __restrict__ fOut,
    float* __restrict__ aOut, float* __restrict__ bOut)
{
    const int M = 4096;
    extern __shared__ float smf[];
    float2* bufA = (float2*)smf;         // F2PAD -> 4352 slots
    float2* bufB = bufA + 4352;
    float2* tw   = bufB + 4352;          // 512 twiddles
    __shared__ float2 red2[64];

    const int be = blockIdx.x;
    const int e  = be & 7;
    const int tid = threadIdx.x;

    const float2* rowc = (const float2*)(latent + (size_t)be * T_LEN);
    const float2* fw0  = (const float2*)(fcW + (size_t)(e * 2 + 0) * T_LEN);
    const float2* fw1  = (const float2*)(fcW + (size_t)(e * 2 + 1) * T_LEN);

    float2 v0 = make_float2(0.f, 0.f), v1 = make_float2(0.f, 0.f);
#pragma unroll
    for (int i = tid; i < M; i += 512) {
        float2 z = rowc[i];
        bufA[F2PAD(i)] = z;
        float2 a0 = fw0[i], a1 = fw1[i];
        v0 = df_addf(v0, z.x * a0.x + z.y * a0.y);
        v1 = df_addf(v1, z.x * a1.x + z.y * a1.y);
    }
    {
        float s, c;
        sincosf(-(float)CUDART_PI * (float)tid / 2048.0f, &s, &c);
        tw[tid] = make_float2(c, s);
    }
    __syncthreads();

    const float RS = 0.70710678118654752440f;
    float2* bin  = bufA;
    float2* bout = bufB;
#pragma unroll
    for (int sg = 0; sg < 4; sg++) {
        const int m = 1 << (3 * sg);
        const int idx = tid;
        const int r = idx & (m - 1);
        float2 W = tw[r << (9 - 3 * sg)];

        float2 u0 = bin[F2PAD(idx)];
        float2 z1 = bin[F2PAD(idx + 512)];
        float2 z2 = bin[F2PAD(idx + 1024)];
        float2 z3 = bin[F2PAD(idx + 1536)];
        float2 z4 = bin[F2PAD(idx + 2048)];
        float2 z5 = bin[F2PAD(idx + 2560)];
        float2 z6 = bin[F2PAD(idx + 3072)];
        float2 z7 = bin[F2PAD(idx + 3584)];

        float2 Wc = W;
        float2 u1 = cmulf(z1, Wc); Wc = cmulf(Wc, W);
        float2 u2 = cmulf(z2, Wc); Wc = cmulf(Wc, W);
        float2 u3 = cmulf(z3, Wc); Wc = cmulf(Wc, W);
        float2 u4 = cmulf(z4, Wc); Wc = cmulf(Wc, W);
        float2 u5 = cmulf(z5, Wc); Wc = cmulf(Wc, W);
        float2 u6 = cmulf(z6, Wc); Wc = cmulf(Wc, W);
        float2 u7 = cmulf(z7, Wc);

        float2 t0 = cadd(u0, u4), t1 = csub(u0, u4);
        float2 t2 = cadd(u2, u6), t3 = csub(u2, u6);
        float2 E0 = cadd(t0, t2);
        float2 E1 = make_float2(t1.x + t3.y, t1.y - t3.x);
        float2 E2 = csub(t0, t2);
        float2 E3 = make_float2(t1.x - t3.y, t1.y + t3.x);
        float2 s0 = cadd(u1, u5), s1 = csub(u1, u5);
        float2 s2 = cadd(u3, u7), s3 = csub(u3, u7);
        float2 O0 = cadd(s0, s2);
        float2 O1 = make_float2(s1.x + s3.y, s1.y - s3.x);
        float2 O2 = csub(s0, s2);
        float2 O3 = make_float2(s1.x - s3.y, s1.y + s3.x);
        float2 Q1 = make_float2(RS * (O1.x + O1.y), RS * (O1.y - O1.x));
        float2 Q2 = make_float2(O2.y, -O2.x);
        float2 Q3 = make_float2(RS * (O3.y - O3.x), -RS * (O3.x + O3.y));

        const int ob = ((idx - r) << 3) + r;
        bout[F2PAD(ob)]         = cadd(E0, O0);
        bout[F2PAD(ob + m)]     = cadd(E1, Q1);
        bout[F2PAD(ob + 2 * m)] = cadd(E2, Q2);
        bout[F2PAD(ob + 3 * m)] = cadd(E3, Q3);
        bout[F2PAD(ob + 4 * m)] = csub(E0, O0);
        bout[F2PAD(ob + 5 * m)] = csub(E1, Q1);
        bout[F2PAD(ob + 6 * m)] = csub(E2, Q2);
        bout[F2PAD(ob + 7 * m)] = csub(E3, Q3);
        __syncthreads();
        float2* tmp = bin; bin = bout; bout = tmp;
    }

    float2 psum = make_float2(0.f, 0.f), wsum = make_float2(0.f, 0.f);
#pragma unroll
    for (int k0 = 0; k0 < 8; k0++) {
        int k = tid + 1 + k0 * 512;
        if (k < M) {
            float2 zk = bin[F2PAD(k)];
            float2 zm = bin[F2PAD(M - k)];
            float Ax = 0.5f * (zk.x + zm.x), Ay = 0.5f * (zk.y - zm.y);
            float Bx = 0.5f * (zk.x - zm.x), By = 0.5f * (zk.y + zm.y);
            float s, c;
            __sincosf(-(float)CUDART_PI * (float)k / (float)M, &s, &c);
            float Xr = Ax + c * By + s * Bx;
            float Xi = Ay - c * Bx + s * By;
            float pw = Xr * Xr + Xi * Xi;
            psum = df_addf(psum, pw);
            wsum = df_addf(wsum, (float)k * pw);
        }
    }
    if (tid == 0) {
        float xm = bin[0].x - bin[0].y;
        psum = df_addf(psum, xm * xm);
        wsum = df_addf(wsum, (float)M * (xm * xm));
    }

    const unsigned mask = 0xffffffffu;
#pragma unroll
    for (int o = 16; o > 0; o >>= 1) {
        psum = df_add(psum, make_float2(__shfl_down_sync(mask, psum.x, o),
                                        __shfl_down_sync(mask, psum.y, o)));
        wsum = df_add(wsum, make_float2(__shfl_down_sync(mask, wsum.x, o),
                                        __shfl_down_sync(mask, wsum.y, o)));
        v0   = df_add(v0,   make_float2(__shfl_down_sync(mask, v0.x, o),
                                        __shfl_down_sync(mask, v0.y, o)));
        v1   = df_add(v1,   make_float2(__shfl_down_sync(mask, v1.x, o),
                                        __shfl_down_sync(mask, v1.y, o)));
    }
    const int warp = tid >> 5, lane = tid & 31;
    if (lane == 0) {
        red2[warp] = psum; red2[16 + warp] = wsum;
        red2[32 + warp] = v0; red2[48 + warp] = v1;
    }
    __syncthreads();
    if (tid == 0) {
        double P = 0, Wm = 0, V0 = 0, V1 = 0;
        for (int i = 0; i < 16; i++) {
            P  += (double)red2[i].x      + (double)red2[i].y;
            Wm += (double)red2[16 + i].x + (double)red2[16 + i].y;
            V0 += (double)red2[32 + i].x + (double)red2[32 + i].y;
            V1 += (double)red2[48 + i].x + (double)red2[48 + i].y;
        }
        V0 += (double)fcb[e * 2];
        V1 += (double)fcb[e * 2 + 1];
        float f    = (float)(0.5 * Wm / P);
        float a    = 2.0f * sqrtf((float)P) / (float)T_LEN;
        float boff = (bin[0].x + bin[0].y) / (float)T_LEN;
        float p    = atan2f((float)V1, (float)V0) / TPI_F;
        pOut[be] = p; fOut[be] = f; aOut[be] = a; bOut[be] = boff;
    }
}

// ---------------------------------------------------------------------------
// Kernel D: sinusoid resynthesis + ANALYTIC deconv tree.
// LTI: sinusoid through the 3 linear conv levels = sinusoid scaled by the
// composed complex frequency response G_e = a_e * H0(f_e) H1(f_e) H2(f_e).
// Interior out(t) = sum_e [Gr_e*sin + Gi_e*cos](theta_e(t)) + C  (C = DC chain).
// Edge samples (21 per side, zero-padding breaks LTI) computed by direct conv.
// ---------------------------------------------------------------------------
__global__ __launch_bounds__(256) void sig_tree_kernel(
    const float* __restrict__ pArr, const float* __restrict__ fArr,
    const float* __restrict__ aArr, const float* __restrict__ bArr,
    const float* __restrict__ dW0, const float* __restrict__ db0,
    const float* __restrict__ dW1, const float* __restrict__ db1,
    const float* __restrict__ dW2, const float* __restrict__ db2,
    float* __restrict__ sig, float* __restrict__ outp)
{
    extern __shared__ float smd[];
    const int SW  = TD + 42;     // 1066 sig slots per pair-row (halo 21)
    const int SPW = TD + 8;      // padded spart row
    float2* ssig2 = (float2*)smd;                 // 4 * SW float2
    float*  spart = (float*)(ssig2 + 4 * SW);     // 4 * SPW floats
    float*  y0e   = spart + 4 * SPW;              // 4 * 36
    float*  y1e   = y0e + 4 * 36;                 // 2 * 28

    __shared__ float sca[8], scf[8], scp[8], scb[8];
    __shared__ float2 rotv[8];
    __shared__ float sGr[8], sGi[8];
    __shared__ float sC;
    __shared__ ull sdw0p[4 * KS], sdw1p[2 * KS], sdw2p[KS];
    __shared__ float sdb0[4], sdb1[2], sdb2s;

    const int blk  = blockIdx.x;
    const int tile = blk & 7;
    const int b    = blk >> 3;
    const int t0   = tile * TD;
    const int tid  = threadIdx.x;
    const float inv = 2.0f / (float)(T_LEN - 1);

    // ---- per-channel params + complex gains G_e ----
    if (tid < 8) {
        const int e = tid;
        float fv = fArr[b * 8 + e];
        float av = aArr[b * 8 + e];
        sca[e] = av; scf[e] = fv;
        scp[e] = pArr[b * 8 + e]; scb[e] = bArr[b * 8 + e];
        float S, C;
        sincospif(2.0f * fv * inv, &S, &C);
        rotv[e] = make_float2(C, S);

        float h0r = 0.f, h0i = 0.f, h1r = 0.f, h1i = 0.f, h2r = 0.f, h2i = 0.f;
        const int row1 = ((e >> 2) << 1) | ((e >> 1) & 1);
        const int row2 = e >> 2;
#pragma unroll
        for (int k = 0; k < KS; k++) {
            float ph = 2.0f * fv * (float)(k - 7) * inv;
            float ss, cc;
            sincospif(ph, &ss, &cc);
            float w0 = dW0[e * KS + k];
            float w1 = dW1[row1 * KS + k];
            float w2 = dW2[row2 * KS + k];
            h0r += w0 * cc; h0i += w0 * ss;
            h1r += w1 * cc; h1i += w1 * ss;
            h2r += w2 * cc; h2i += w2 * ss;
        }
        float g1r = h0r * h1r - h0i * h1i;
        float g1i = h0r * h1i + h0i * h1r;
        sGr[e] = av * (g1r * h2r - g1i * h2i);
        sGi[e] = av * (g1r * h2i + g1i * h2r);
    }
    // ---- DC constant C ----
    if (tid == 8) {
        float S0[8], S1[4], S2[2];
        for (int e2 = 0; e2 < 8; e2++) {
            float s = 0.f;
            for (int k = 0; k < KS; k++) s += dW0[e2 * KS + k];
            S0[e2] = s;
        }
        for (int g = 0; g < 4; g++) {
            float s = 0.f;
            for (int k = 0; k < KS; k++) s += dW1[g * KS + k];
            S1[g] = s;
        }
        for (int q = 0; q < 2; q++) {
            float s = 0.f;
            for (int k = 0; k < KS; k++) s += dW2[q * KS + k];
            S2[q] = s;
        }
        float Cv = db2[0];
        for (int q = 0; q < 2; q++) Cv += S2[q] * db1[q];
        for (int g = 0; g < 4; g++) Cv += S2[g >> 1] * S1[g] * db0[g];
        for (int e2 = 0; e2 < 8; e2++)
            Cv += S2[e2 >> 2] * S1[e2 >> 1] * S0[e2] * bArr[b * 8 + e2];
        sC = Cv;
    }
    if (tid < 4 * KS) {
        int g = tid / KS, k = tid - g * KS;
        sdw0p[tid] = pk2(dW0[(2 * g) * KS + k], dW0[(2 * g + 1) * KS + k]);
    }
    if (tid < 2 * KS) {
        int g = tid / KS, k = tid - g * KS;
        sdw1p[tid] = pk2(dW1[(2 * g) * KS + k], dW1[(2 * g + 1) * KS + k]);
    }
    if (tid < KS) sdw2p[tid] = pk2(dW2[tid], dW2[KS + tid]);
    if (tid < 4) sdb0[tid] = db0[tid];
    if (tid < 2) sdb1[tid] = db1[tid];
    if (tid == 0) sdb2s = db2[0];
    __syncthreads();

    // ---- generation: sig values + analytic out partials ----
    {
        const int pr  = tid >> 6;
        const int sub = tid & 63;
        const int j0  = sub * 17;
        const int ts  = t0 - 21 + j0;
        const int e0 = 2 * pr, e1 = 2 * pr + 1;
        const float arg0 = -1.0f + (float)ts * inv;
        float s0, c0, s1, c1;
        sincospif(2.0f * (scf[e0] * arg0 + scp[e0]), &s0, &c0);
        sincospif(2.0f * (scf[e1] * arg0 + scp[e1]), &s1, &c1);
        const float2 r0 = rotv[e0], r1 = rotv[e1];
        const float a0 = sca[e0], b0 = scb[e0];
        const float a1 = sca[e1], b1v = scb[e1];
        const float gr0 = sGr[e0], gi0 = sGi[e0];
        const float gr1 = sGr[e1], gi1 = sGi[e1];
        float* sprow = spart + pr * SPW;
#pragma unroll
        for (int jj = 0; jj < 17; jj++) {
            int j = j0 + jj;
            int t = ts + jj;
            if (j < SW) {
                bool ok = ((unsigned)t < (unsigned)T_LEN);
                float v0 = ok ? (a0 * s0 + b0)  : 0.f;
                float v1 = ok ? (a1 * s1 + b1v) : 0.f;
                ssig2[pr * SW + j] = make_float2(v0, v1);
                if (j >= 21 && j < 21 + TD)
                    sprow[j - 21] = gr0 * s0 + gi0 * c0 + gr1 * s1 + gi1 * c1;
            }
            float ns0 = s0 * r0.x + c0 * r0.y;
            c0 = c0 * r0.x - s0 * r0.y; s0 = ns0;
            float ns1 = s1 * r1.x + c1 * r1.y;
            c1 = c1 * r1.x - s1 * r1.y; s1 = ns1;
        }
    }
    __syncthreads();

    // ---- coalesced sig writeback ----
    for (int i = tid; i < 8 * TD; i += 256) {
        int e = i >> 10, jj = i & (TD - 1);
        float2 v = ssig2[(e >> 1) * SW + 21 + jj];
        sig[((size_t)b * 8 + e) * T_LEN + t0 + jj] = (e & 1) ? v.y : v.x;
    }

    // ---- interior out: sum of 4 partials + C ----
    {
        const float Cv = sC;
        const bool left  = (tile == 0);
        const bool right = (tile == 7);
        float* orow = outp + (size_t)b * T_LEN + t0;
#pragma unroll
        for (int jj = tid; jj < TD; jj += 256) {
            bool skip = (left && jj < 21) || (right && jj >= TD - 21);
            if (!skip) {
                orow[jj] = spart[jj] + spart[SPW + jj] +
                           spart[2 * SPW + jj] + spart[3 * SPW + jj] + Cv;
            }
        }
    }

    // ---- edge fix: direct 3-level conv for 21 samples per side ----
    {
        const bool left  = (tile == 0);
        const bool right = (tile == 7);
        const bool edge  = left || right;

        // level 0: y0e[g][j], j in [0,35); global J = left ? j : T-35+j
        if (edge && tid < 140) {
            const int g = tid / 35, j = tid - g * 35;
            float acc = sdb0[g];
#pragma unroll
            for (int k = 0; k < KS; k++) {
                int tG = (left ? j : (T_LEN - 35 + j)) + k - 7;
                int slot = tG - t0 + 21;          // halo zeros cover out-of-range
                float2 w = unpk2(sdw0p[g * KS + k]);
                float2 sv = ssig2[g * SW + slot];
                acc += w.x * sv.x + w.y * sv.y;
            }
            y0e[g * 36 + j] = acc;
        }
        __syncthreads();

        // level 1: y1e[g1][j], j in [0,28)
        if (edge && tid < 56) {
            const int g1 = tid / 28, j = tid - g1 * 28;
            float acc = sdb1[g1];
#pragma unroll
            for (int k = 0; k < KS; k++) {
                int idx; bool ok;
                if (left) { idx = j + k - 7; ok = (idx >= 0); }
                else      { idx = j + k;     ok = (idx < 35); }
                if (ok) {
                    float2 w = unpk2(sdw1p[g1 * KS + k]);
                    acc += w.x * y0e[(2 * g1) * 36 + idx]
                         + w.y * y0e[(2 * g1 + 1) * 36 + idx];
                }
            }
            y1e[g1 * 28 + j] = acc;
        }
        __syncthreads();

        // level 2: out edge samples
        if (edge && tid < 21) {
            float acc = sdb2s;
#pragma unroll
            for (int k = 0; k < KS; k++) {
                int idx; bool ok;
                if (left) { idx = tid + k - 7; ok = (idx >= 0); }
                else      { idx = tid + k;     ok = (idx < 28); }
                if (ok) {
                    float2 w = unpk2(sdw2p[k]);
                    acc += w.x * y1e[idx] + w.y * y1e[28 + idx];
                }
            }
            int tG = left ? tid : (T_LEN - 21 + tid);
            outp[(size_t)b * T_LEN + tG] = acc;
        }
    }
}

// ---------------------------------------------------------------------------
extern "C" void kernel_launch(void* const* d_in, const int* in_sizes, int n_in,
                              void* d_out, int out_size)
{
    const float* x   = (const float*)d_in[0];
    const float* W1  = (const float*)d_in[1];
    const float* b1  = (const float*)d_in[2];
    const float* W2  = (const float*)d_in[3];
    const float* b2  = (const float*)d_in[4];
    const float* fcW = (const float*)d_in[5];
    const float* fcb = (const float*)d_in[6];
    const float* dW0 = (const float*)d_in[7];
    const float* db0 = (const float*)d_in[8];
    const float* dW1 = (const float*)d_in[9];
    const float* db1 = (const float*)d_in[10];
    const float* dW2 = (const float*)d_in[11];
    const float* db2 = (const float*)d_in[12];

    float* out = (float*)d_out;
    float* outMain = out;                                        // (B, T)
    float* latent  = out + (size_t)B_SZ * T_LEN;                 // (B, E, T)
    float* sig     = latent + (size_t)B_SZ * E_CH * T_LEN;       // (B, E, T)
    float* pOut    = sig + (size_t)B_SZ * E_CH * T_LEN;          // (B, E, 1)
    float* fOut    = pOut + B_SZ * E_CH;
    float* aOut    = fOut + B_SZ * E_CH;
    float* bOut    = aOut + B_SZ * E_CH;

    const size_t smA = (size_t)8448 * sizeof(float) + (size_t)8704 * sizeof(ull);
    const size_t smB = (size_t)(4352 * 2 + 512) * sizeof(float2);
    const size_t smD = (size_t)(4 * (TD + 42)) * sizeof(float2)
                     + (size_t)(4 * (TD + 8) + 4 * 36 + 2 * 28) * sizeof(float);

    cudaFuncSetAttribute(latent_kernel,   cudaFuncAttributeMaxDynamicSharedMemorySize, (int)smA);
    cudaFuncSetAttribute(fft_kernel,      cudaFuncAttributeMaxDynamicSharedMemorySize, (int)smB);
    cudaFuncSetAttribute(sig_tree_kernel, cudaFuncAttributeMaxDynamicSharedMemorySize, (int)smD);

    latent_kernel<<<B_SZ * E_CH, 256, smA>>>(x, W1, b1, W2, b2, latent);
    fft_kernel<<<B_SZ * E_CH, 512, smB>>>(latent, fcW, fcb, pOut, fOut, aOut, bOut);
    sig_tree_kernel<<<B_SZ * (T_LEN / TD), 256, smD>>>(pOut, fOut, aOut, bOut,
                                                       dW0, db0, dW1, db1, dW2, db2,
                                                       sig, outMain);
}

// round 10
// speedup vs baseline: 1.2222x; 1.0081x over previous
#include <cuda_runtime.h>
#include <math_constants.h>

#define T_LEN 8192
#define B_SZ  256
#define E_CH  8
#define KS    15
#define TD    1024
#define TPI_F 6.28318530717958647692f

#define PAD(i)   ((i) + ((i) >> 5))
#define F2PAD(i) ((i) + ((i) >> 4))

typedef unsigned long long ull;

// ---- packed f32x2 helpers ----
__device__ __forceinline__ ull pk2(float lo, float hi) {
    ull r;
    asm("mov.b64 %0, {%1, %2};" : "=l"(r) : "f"(lo), "f"(hi));
    return r;
}
__device__ __forceinline__ float2 unpk2(ull v) {
    float lo, hi;
    asm("mov.b64 {%0, %1}, %2;" : "=f"(lo), "=f"(hi) : "l"(v));
    return make_float2(lo, hi);
}
__device__ __forceinline__ ull fma2(ull a, ull b, ull c) {
    ull d;
    asm("fma.rn.f32x2 %0, %1, %2, %3;" : "=l"(d) : "l"(a), "l"(b), "l"(c));
    return d;
}
__device__ __forceinline__ ull add2(ull a, ull b) {
    ull d;
    asm("add.rn.f32x2 %0, %1, %2;" : "=l"(d) : "l"(a), "l"(b));
    return d;
}

__device__ __forceinline__ float2 cmulf(float2 a, float2 b) {
    return make_float2(a.x * b.x - a.y * b.y, a.x * b.y + a.y * b.x);
}
__device__ __forceinline__ float2 cadd(float2 a, float2 b) {
    return make_float2(a.x + b.x, a.y + b.y);
}
__device__ __forceinline__ float2 csub(float2 a, float2 b) {
    return make_float2(a.x - b.x, a.y - b.y);
}

// compensated float-float accumulation (TwoSum based)
__device__ __forceinline__ float2 df_add(float2 a, float2 b) {
    float s = a.x + b.x;
    float v = s - a.x;
    float e = (a.x - (s - v)) + (b.x - v);
    e = e + a.y + b.y;
    float hi = s + e;
    return make_float2(hi, e - (hi - s));
}
__device__ __forceinline__ float2 df_addf(float2 a, float b) {
    return df_add(a, make_float2(b, 0.f));
}

// ---------------------------------------------------------------------------
// Kernel A: fused per-channel dilated conv pair -> latent (B,E,T)
// Coset-blocked register streaming + packed f32x2 math. (R5 proven body.)
// ---------------------------------------------------------------------------
__global__ __launch_bounds__(256, 2) void latent_kernel(
    const float* __restrict__ x,
    const float* __restrict__ W1, const float* __restrict__ b1,
    const float* __restrict__ W2, const float* __restrict__ b2,
    float* __restrict__ latent)
{
    extern __shared__ float sm[];
    float* sx  = sm;                               // PAD(8192) -> 8448 floats
    ull*   shp = (ull*)(sm + 8448);                // F2PAD(8192) -> 8704 ull

    const int be = blockIdx.x;
    const int e  = be & 7;
    const int b  = be >> 3;
    const int d  = 1 << e;
    const int tid = threadIdx.x;

    const float* xrow = x + (size_t)b * T_LEN;
    for (int i = tid; i < T_LEN; i += 256) sx[PAD(i)] = xrow[i];

    ull w1pk[KS];
#pragma unroll
    for (int j = 0; j < KS; j++)
        w1pk[j] = pk2(W1[e * 30 + j], W1[e * 30 + 15 + j]);
    const ull bias1 = pk2(b1[2 * e], b1[2 * e + 1]);
    __syncthreads();

#pragma unroll 1
    for (int it = 0; it < 4; it++) {
        const int cc = it * 256 + tid;
        const int p  = cc & (d - 1);
        const int qc = cc >> e;
        const int tb = p + (qc << (e + 3));
        ull xd[22];
#pragma unroll
        for (int m = 0; m < 22; m++) {
            int idx = tb + (m - 7) * d;
            float v = ((unsigned)idx < (unsigned)T_LEN) ? sx[PAD(idx)] : 0.f;
            xd[m] = pk2(v, v);
        }
#pragma unroll
        for (int rr = 0; rr < 8; rr++) {
            ull a0 = bias1, a1 = 0ULL;
#pragma unroll
            for (int j = 0; j < KS; j += 2) a0 = fma2(w1pk[j], xd[rr + j], a0);
#pragma unroll
            for (int j = 1; j < KS; j += 2) a1 = fma2(w1pk[j], xd[rr + j], a1);
            shp[F2PAD(tb + rr * d)] = add2(a0, a1);
        }
    }

    ull w2pk[KS];
#pragma unroll
    for (int k = 0; k < KS; k++)
        w2pk[k] = pk2(W2[e * 30 + k], W2[e * 30 + 15 + k]);
    const ull bias2 = pk2(b2[e], 0.f);
    __syncthreads();

#pragma unroll 1
    for (int it = 0; it < 4; it++) {
        const int cc = it * 256 + tid;
        const int p  = cc & (d - 1);
        const int qc = cc >> e;
        const int tb = p + (qc << (e + 3));
        ull gp[22];
#pragma unroll
        for (int m = 0; m < 22; m++) {
            int idx = tb + (m - 7) * d;
            gp[m] = ((unsigned)idx < (unsigned)T_LEN) ? shp[F2PAD(idx)] : 0ULL;
        }
#pragma unroll
        for (int rr = 0; rr < 8; rr++) {
            ull a0 = bias2, a1 = 0ULL;
#pragma unroll
            for (int k = 0; k < KS; k += 2) a0 = fma2(w2pk[k], gp[rr + k], a0);
#pragma unroll
            for (int k = 1; k < KS; k += 2) a1 = fma2(w2pk[k], gp[rr + k], a1);
            float2 r = unpk2(add2(a0, a1));
            sx[PAD(tb + rr * d)] = r.x + r.y;
        }
    }
    __syncthreads();

    float* lrow = latent + (size_t)be * T_LEN;
    for (int i = tid; i < T_LEN; i += 256) lrow[i] = sx[PAD(i)];
}

// ---------------------------------------------------------------------------
// Kernel B: per-(b,e) row — fc dots, real FFT (8192 real via complex 4096),
// radix-8 Stockham. Stage 0 fused with the global load (twiddle-free DFT-8
// in registers), last stage keeps natural-order outputs in registers so the
// reduction only loads conjugate partners. Compensated fp32 reductions.
// ---------------------------------------------------------------------------
__global__ __launch_bounds__(512, 2) void fft_kernel(
    const float* __restrict__ latent,
    const float* __restrict__ fcW, const float* __restrict__ fcb,
    float* __restrict__ pOut, float* __restrict__ fOut,
    float* __restrict__ aOut, float* __restrict__ bOut)
{
    const int M = 4096;
    extern __shared__ float smf[];
    float2* bufA = (float2*)smf;         // F2PAD -> 4352 slots
    float2* bufB = bufA + 4352;
    float2* tw   = bufB + 4352;          // 512 twiddles
    __shared__ float2 red2[64];

    const int be = blockIdx.x;
    const int e  = be & 7;
    const int tid = threadIdx.x;
    const float RS = 0.70710678118654752440f;

    const float2* rowc = (const float2*)(latent + (size_t)be * T_LEN);
    const float2* fw0  = (const float2*)(fcW + (size_t)(e * 2 + 0) * T_LEN);
    const float2* fw1  = (const float2*)(fcW + (size_t)(e * 2 + 1) * T_LEN);

    // ---- fused: global load + fc dots + stage 0 (twiddles unity) ----
    float2 v0 = make_float2(0.f, 0.f), v1 = make_float2(0.f, 0.f);
    float2 z[8];
#pragma unroll
    for (int q = 0; q < 8; q++) {
        const int i = tid + 512 * q;
        float2 zz = rowc[i];
        z[q] = zz;
        float2 a0 = fw0[i], a1 = fw1[i];
        v0 = df_addf(v0, zz.x * a0.x + zz.y * a0.y);
        v1 = df_addf(v1, zz.x * a1.x + zz.y * a1.y);
    }
    {
        float s, c;
        sincosf(-(float)CUDART_PI * (float)tid / 2048.0f, &s, &c);
        tw[tid] = make_float2(c, s);
    }
    {
        float2 t0 = cadd(z[0], z[4]), t1 = csub(z[0], z[4]);
        float2 t2 = cadd(z[2], z[6]), t3 = csub(z[2], z[6]);
        float2 E0 = cadd(t0, t2);
        float2 E1 = make_float2(t1.x + t3.y, t1.y - t3.x);
        float2 E2 = csub(t0, t2);
        float2 E3 = make_float2(t1.x - t3.y, t1.y + t3.x);
        float2 s0 = cadd(z[1], z[5]), s1 = csub(z[1], z[5]);
        float2 s2 = cadd(z[3], z[7]), s3 = csub(z[3], z[7]);
        float2 O0 = cadd(s0, s2);
        float2 O1 = make_float2(s1.x + s3.y, s1.y - s3.x);
        float2 O2 = csub(s0, s2);
        float2 O3 = make_float2(s1.x - s3.y, s1.y + s3.x);
        float2 Q1 = make_float2(RS * (O1.x + O1.y), RS * (O1.y - O1.x));
        float2 Q2 = make_float2(O2.y, -O2.x);
        float2 Q3 = make_float2(RS * (O3.y - O3.x), -RS * (O3.x + O3.y));
        const int ob = tid << 3;
        bufA[F2PAD(ob)]     = cadd(E0, O0);
        bufA[F2PAD(ob + 1)] = cadd(E1, Q1);
        bufA[F2PAD(ob + 2)] = cadd(E2, Q2);
        bufA[F2PAD(ob + 3)] = cadd(E3, Q3);
        bufA[F2PAD(ob + 4)] = csub(E0, O0);
        bufA[F2PAD(ob + 5)] = csub(E1, Q1);
        bufA[F2PAD(ob + 6)] = csub(E2, Q2);
        bufA[F2PAD(ob + 7)] = csub(E3, Q3);
    }
    __syncthreads();

    // ---- stages 1,2: bufA -> bufB -> bufA ----
    float2* bin  = bufA;
    float2* bout = bufB;
#pragma unroll
    for (int sg = 1; sg <= 2; sg++) {
        const int m = 1 << (3 * sg);
        const int idx = tid;
        const int r = idx & (m - 1);
        float2 W = tw[r << (9 - 3 * sg)];

        float2 u0 = bin[F2PAD(idx)];
        float2 z1 = bin[F2PAD(idx + 512)];
        float2 z2 = bin[F2PAD(idx + 1024)];
        float2 z3 = bin[F2PAD(idx + 1536)];
        float2 z4 = bin[F2PAD(idx + 2048)];
        float2 z5 = bin[F2PAD(idx + 2560)];
        float2 z6 = bin[F2PAD(idx + 3072)];
        float2 z7 = bin[F2PAD(idx + 3584)];

        float2 W2 = cmulf(W, W);
        float2 W3 = cmulf(W2, W);
        float2 W4 = cmulf(W2, W2);
        float2 W5 = cmulf(W4, W);
        float2 W6 = cmulf(W4, W2);
        float2 W7 = cmulf(W4, W3);

        float2 u1 = cmulf(z1, W);
        float2 u2 = cmulf(z2, W2);
        float2 u3 = cmulf(z3, W3);
        float2 u4 = cmulf(z4, W4);
        float2 u5 = cmulf(z5, W5);
        float2 u6 = cmulf(z6, W6);
        float2 u7 = cmulf(z7, W7);

        float2 t0 = cadd(u0, u4), t1 = csub(u0, u4);
        float2 t2 = cadd(u2, u6), t3 = csub(u2, u6);
        float2 E0 = cadd(t0, t2);
        float2 E1 = make_float2(t1.x + t3.y, t1.y - t3.x);
        float2 E2 = csub(t0, t2);
        float2 E3 = make_float2(t1.x - t3.y, t1.y + t3.x);
        float2 s0 = cadd(u1, u5), s1 = csub(u1, u5);
        float2 s2 = cadd(u3, u7), s3 = csub(u3, u7);
        float2 O0 = cadd(s0, s2);
        float2 O1 = make_float2(s1.x + s3.y, s1.y - s3.x);
        float2 O2 = csub(s0, s2);
        float2 O3 = make_float2(s1.x - s3.y, s1.y + s3.x);
        float2 Q1 = make_float2(RS * (O1.x + O1.y), RS * (O1.y - O1.x));
        float2 Q2 = make_float2(O2.y, -O2.x);
        float2 Q3 = make_float2(RS * (O3.y - O3.x), -RS * (O3.x + O3.y));

        const int ob = ((idx - r) << 3) + r;
        bout[F2PAD(ob)]         = cadd(E0, O0);
        bout[F2PAD(ob + m)]     = cadd(E1, Q1);
        bout[F2PAD(ob + 2 * m)] = cadd(E2, Q2);
        bout[F2PAD(ob + 3 * m)] = cadd(E3, Q3);
        bout[F2PAD(ob + 4 * m)] = csub(E0, O0);
        bout[F2PAD(ob + 5 * m)] = csub(E1, Q1);
        bout[F2PAD(ob + 6 * m)] = csub(E2, Q2);
        bout[F2PAD(ob + 7 * m)] = csub(E3, Q3);
        __syncthreads();
        float2* tmp = bin; bin = bout; bout = tmp;
    }
    // bin = bufA holds stage-2 output

    // ---- stage 3 (last): natural-order outputs kept in registers ----
    // k of zo[q] = tid + 512*q
    {
        const int idx = tid;
        float2 W = tw[idx];              // r = idx, shift 0

        float2 u0 = bin[F2PAD(idx)];
        float2 z1 = bin[F2PAD(idx + 512)];
        float2 z2 = bin[F2PAD(idx + 1024)];
        float2 z3 = bin[F2PAD(idx + 1536)];
        float2 z4 = bin[F2PAD(idx + 2048)];
        float2 z5 = bin[F2PAD(idx + 2560)];
        float2 z6 = bin[F2PAD(idx + 3072)];
        float2 z7 = bin[F2PAD(idx + 3584)];

        float2 W2 = cmulf(W, W);
        float2 W3 = cmulf(W2, W);
        float2 W4 = cmulf(W2, W2);
        float2 W5 = cmulf(W4, W);
        float2 W6 = cmulf(W4, W2);
        float2 W7 = cmulf(W4, W3);

        float2 u1 = cmulf(z1, W);
        float2 u2 = cmulf(z2, W2);
        float2 u3 = cmulf(z3, W3);
        float2 u4 = cmulf(z4, W4);
        float2 u5 = cmulf(z5, W5);
        float2 u6 = cmulf(z6, W6);
        float2 u7 = cmulf(z7, W7);

        float2 t0 = cadd(u0, u4), t1 = csub(u0, u4);
        float2 t2 = cadd(u2, u6), t3 = csub(u2, u6);
        float2 E0 = cadd(t0, t2);
        float2 E1 = make_float2(t1.x + t3.y, t1.y - t3.x);
        float2 E2 = csub(t0, t2);
        float2 E3 = make_float2(t1.x - t3.y, t1.y + t3.x);
        float2 s0 = cadd(u1, u5), s1 = csub(u1, u5);
        float2 s2 = cadd(u3, u7), s3 = csub(u3, u7);
        float2 O0 = cadd(s0, s2);
        float2 O1 = make_float2(s1.x + s3.y, s1.y - s3.x);
        float2 O2 = csub(s0, s2);
        float2 O3 = make_float2(s1.x - s3.y, s1.y + s3.x);
        float2 Q1 = make_float2(RS * (O1.x + O1.y), RS * (O1.y - O1.x));
        float2 Q2 = make_float2(O2.y, -O2.x);
        float2 Q3 = make_float2(RS * (O3.y - O3.x), -RS * (O3.x + O3.y));

        z[0] = cadd(E0, O0); z[1] = cadd(E1, Q1);
        z[2] = cadd(E2, Q2); z[3] = cadd(E3, Q3);
        z[4] = csub(E0, O0); z[5] = csub(E1, Q1);
        z[6] = csub(E2, Q2); z[7] = csub(E3, Q3);
#pragma unroll
        for (int q = 0; q < 8; q++)
            bout[F2PAD(idx + 512 * q)] = z[q];
    }
    __syncthreads();
    // bout = bufB holds Z_k natural order; thread tid holds z[q] = Z_{tid+512q}

    float2 psum = make_float2(0.f, 0.f), wsum = make_float2(0.f, 0.f);
#pragma unroll
    for (int q = 0; q < 8; q++) {
        const int k = tid + 512 * q;
        if (k > 0) {
            float2 zk = z[q];
            float2 zm = bout[F2PAD(M - k)];
            float Ax = 0.5f * (zk.x + zm.x), Ay = 0.5f * (zk.y - zm.y);
            float Bx = 0.5f * (zk.x - zm.x), By = 0.5f * (zk.y + zm.y);
            float s, c;
            __sincosf(-(float)CUDART_PI * (float)k / (float)M, &s, &c);
            float Xr = Ax + c * By + s * Bx;
            float Xi = Ay - c * Bx + s * By;
            float pw = Xr * Xr + Xi * Xi;
            psum = df_addf(psum, pw);
            wsum = df_addf(wsum, (float)k * pw);
        }
    }
    if (tid == 0) {
        float xm = z[0].x - z[0].y;       // Nyquist (real)
        psum = df_addf(psum, xm * xm);
        wsum = df_addf(wsum, (float)M * (xm * xm));
    }

    const unsigned mask = 0xffffffffu;
#pragma unroll
    for (int o = 16; o > 0; o >>= 1) {
        psum = df_add(psum, make_float2(__shfl_down_sync(mask, psum.x, o),
                                        __shfl_down_sync(mask, psum.y, o)));
        wsum = df_add(wsum, make_float2(__shfl_down_sync(mask, wsum.x, o),
                                        __shfl_down_sync(mask, wsum.y, o)));
        v0   = df_add(v0,   make_float2(__shfl_down_sync(mask, v0.x, o),
                                        __shfl_down_sync(mask, v0.y, o)));
        v1   = df_add(v1,   make_float2(__shfl_down_sync(mask, v1.x, o),
                                        __shfl_down_sync(mask, v1.y, o)));
    }
    const int warp = tid >> 5, lane = tid & 31;
    if (lane == 0) {
        red2[warp] = psum; red2[16 + warp] = wsum;
        red2[32 + warp] = v0; red2[48 + warp] = v1;
    }
    __syncthreads();
    if (tid == 0) {
        double P = 0, Wm = 0, V0 = 0, V1 = 0;
        for (int i = 0; i < 16; i++) {
            P  += (double)red2[i].x      + (double)red2[i].y;
            Wm += (double)red2[16 + i].x + (double)red2[16 + i].y;
            V0 += (double)red2[32 + i].x + (double)red2[32 + i].y;
            V1 += (double)red2[48 + i].x + (double)red2[48 + i].y;
        }
        V0 += (double)fcb[e * 2];
        V1 += (double)fcb[e * 2 + 1];
        float f    = (float)(0.5 * Wm / P);
        float a    = 2.0f * sqrtf((float)P) / (float)T_LEN;
        float boff = (z[0].x + z[0].y) / (float)T_LEN;   // Z_0 in regs
        float p    = atan2f((float)V1, (float)V0) / TPI_F;
        pOut[be] = p; fOut[be] = f; aOut[be] = a; bOut[be] = boff;
    }
}

// ---------------------------------------------------------------------------
// Kernel D: sinusoid resynthesis + ANALYTIC deconv tree. (R9 proven version.)
// ---------------------------------------------------------------------------
__global__ __launch_bounds__(256) void sig_tree_kernel(
    const float* __restrict__ pArr, const float* __restrict__ fArr,
    const float* __restrict__ aArr, const float* __restrict__ bArr,
    const float* __restrict__ dW0, const float* __restrict__ db0,
    const float* __restrict__ dW1, const float* __restrict__ db1,
    const float* __restrict__ dW2, const float* __restrict__ db2,
    float* __restrict__ sig, float* __restrict__ outp)
{
    extern __shared__ float smd[];
    const int SW  = TD + 42;     // 1066 sig slots per pair-row (halo 21)
    const int SPW = TD + 8;      // padded spart row
    float2* ssig2 = (float2*)smd;                 // 4 * SW float2
    float*  spart = (float*)(ssig2 + 4 * SW);     // 4 * SPW floats
    float*  y0e   = spart + 4 * SPW;              // 4 * 36
    float*  y1e   = y0e + 4 * 36;                 // 2 * 28

    __shared__ float sca[8], scf[8], scp[8], scb[8];
    __shared__ float2 rotv[8];
    __shared__ float sGr[8], sGi[8];
    __shared__ float sC;
    __shared__ ull sdw0p[4 * KS], sdw1p[2 * KS], sdw2p[KS];
    __shared__ float sdb0[4], sdb1[2], sdb2s;

    const int blk  = blockIdx.x;
    const int tile = blk & 7;
    const int b    = blk >> 3;
    const int t0   = tile * TD;
    const int tid  = threadIdx.x;
    const float inv = 2.0f / (float)(T_LEN - 1);

    if (tid < 8) {
        const int e = tid;
        float fv = fArr[b * 8 + e];
        float av = aArr[b * 8 + e];
        sca[e] = av; scf[e] = fv;
        scp[e] = pArr[b * 8 + e]; scb[e] = bArr[b * 8 + e];
        float S, C;
        sincospif(2.0f * fv * inv, &S, &C);
        rotv[e] = make_float2(C, S);

        float h0r = 0.f, h0i = 0.f, h1r = 0.f, h1i = 0.f, h2r = 0.f, h2i = 0.f;
        const int row1 = ((e >> 2) << 1) | ((e >> 1) & 1);
        const int row2 = e >> 2;
#pragma unroll
        for (int k = 0; k < KS; k++) {
            float ph = 2.0f * fv * (float)(k - 7) * inv;
            float ss, cc;
            sincospif(ph, &ss, &cc);
            float w0 = dW0[e * KS + k];
            float w1 = dW1[row1 * KS + k];
            float w2 = dW2[row2 * KS + k];
            h0r += w0 * cc; h0i += w0 * ss;
            h1r += w1 * cc; h1i += w1 * ss;
            h2r += w2 * cc; h2i += w2 * ss;
        }
        float g1r = h0r * h1r - h0i * h1i;
        float g1i = h0r * h1i + h0i * h1r;
        sGr[e] = av * (g1r * h2r - g1i * h2i);
        sGi[e] = av * (g1r * h2i + g1i * h2r);
    }
    if (tid == 8) {
        float S0[8], S1[4], S2[2];
        for (int e2 = 0; e2 < 8; e2++) {
            float s = 0.f;
            for (int k = 0; k < KS; k++) s += dW0[e2 * KS + k];
            S0[e2] = s;
        }
        for (int g = 0; g < 4; g++) {
            float s = 0.f;
            for (int k = 0; k < KS; k++) s += dW1[g * KS + k];
            S1[g] = s;
        }
        for (int q = 0; q < 2; q++) {
            float s = 0.f;
            for (int k = 0; k < KS; k++) s += dW2[q * KS + k];
            S2[q] = s;
        }
        float Cv = db2[0];
        for (int q = 0; q < 2; q++) Cv += S2[q] * db1[q];
        for (int g = 0; g < 4; g++) Cv += S2[g >> 1] * S1[g] * db0[g];
        for (int e2 = 0; e2 < 8; e2++)
            Cv += S2[e2 >> 2] * S1[e2 >> 1] * S0[e2] * bArr[b * 8 + e2];
        sC = Cv;
    }
    if (tid < 4 * KS) {
        int g = tid / KS, k = tid - g * KS;
        sdw0p[tid] = pk2(dW0[(2 * g) * KS + k], dW0[(2 * g + 1) * KS + k]);
    }
    if (tid < 2 * KS) {
        int g = tid / KS, k = tid - g * KS;
        sdw1p[tid] = pk2(dW1[(2 * g) * KS + k], dW1[(2 * g + 1) * KS + k]);
    }
    if (tid < KS) sdw2p[tid] = pk2(dW2[tid], dW2[KS + tid]);
    if (tid < 4) sdb0[tid] = db0[tid];
    if (tid < 2) sdb1[tid] = db1[tid];
    if (tid == 0) sdb2s = db2[0];
    __syncthreads();

    {
        const int pr  = tid >> 6;
        const int sub = tid & 63;
        const int j0  = sub * 17;
        const int ts  = t0 - 21 + j0;
        const int e0 = 2 * pr, e1 = 2 * pr + 1;
        const float arg0 = -1.0f + (float)ts * inv;
        float s0, c0, s1, c1;
        sincospif(2.0f * (scf[e0] * arg0 + scp[e0]), &s0, &c0);
        sincospif(2.0f * (scf[e1] * arg0 + scp[e1]), &s1, &c1);
        const float2 r0 = rotv[e0], r1 = rotv[e1];
        const float a0 = sca[e0], b0 = scb[e0];
        const float a1 = sca[e1], b1v = scb[e1];
        const float gr0 = sGr[e0], gi0 = sGi[e0];
        const float gr1 = sGr[e1], gi1 = sGi[e1];
        float* sprow = spart + pr * SPW;
#pragma unroll
        for (int jj = 0; jj < 17; jj++) {
            int j = j0 + jj;
            int t = ts + jj;
            if (j < SW) {
                bool ok = ((unsigned)t < (unsigned)T_LEN);
                float v0 = ok ? (a0 * s0 + b0)  : 0.f;
                float v1 = ok ? (a1 * s1 + b1v) : 0.f;
                ssig2[pr * SW + j] = make_float2(v0, v1);
                if (j >= 21 && j < 21 + TD)
                    sprow[j - 21] = gr0 * s0 + gi0 * c0 + gr1 * s1 + gi1 * c1;
            }
            float ns0 = s0 * r0.x + c0 * r0.y;
            c0 = c0 * r0.x - s0 * r0.y; s0 = ns0;
            float ns1 = s1 * r1.x + c1 * r1.y;
            c1 = c1 * r1.x - s1 * r1.y; s1 = ns1;
        }
    }
    __syncthreads();

    for (int i = tid; i < 8 * TD; i += 256) {
        int e = i >> 10, jj = i & (TD - 1);
        float2 v = ssig2[(e >> 1) * SW + 21 + jj];
        sig[((size_t)b * 8 + e) * T_LEN + t0 + jj] = (e & 1) ? v.y : v.x;
    }

    {
        const float Cv = sC;
        const bool left  = (tile == 0);
        const bool right = (tile == 7);
        float* orow = outp + (size_t)b * T_LEN + t0;
#pragma unroll
        for (int jj = tid; jj < TD; jj += 256) {
            bool skip = (left && jj < 21) || (right && jj >= TD - 21);
            if (!skip) {
                orow[jj] = spart[jj] + spart[SPW + jj] +
                           spart[2 * SPW + jj] + spart[3 * SPW + jj] + Cv;
            }
        }
    }

    {
        const bool left  = (tile == 0);
        const bool right = (tile == 7);
        const bool edge  = left || right;

        if (edge && tid < 140) {
            const int g = tid / 35, j = tid - g * 35;
            float acc = sdb0[g];
#pragma unroll
            for (int k = 0; k < KS; k++) {
                int tG = (left ? j : (T_LEN - 35 + j)) + k - 7;
                int slot = tG - t0 + 21;
                float2 w = unpk2(sdw0p[g * KS + k]);
                float2 sv = ssig2[g * SW + slot];
                acc += w.x * sv.x + w.y * sv.y;
            }
            y0e[g * 36 + j] = acc;
        }
        __syncthreads();

        if (edge && tid < 56) {
            const int g1 = tid / 28, j = tid - g1 * 28;
            float acc = sdb1[g1];
#pragma unroll
            for (int k = 0; k < KS; k++) {
                int idx; bool ok;
                if (left) { idx = j + k - 7; ok = (idx >= 0); }
                else      { idx = j + k;     ok = (idx < 35); }
                if (ok) {
                    float2 w = unpk2(sdw1p[g1 * KS + k]);
                    acc += w.x * y0e[(2 * g1) * 36 + idx]
                         + w.y * y0e[(2 * g1 + 1) * 36 + idx];
                }
            }
            y1e[g1 * 28 + j] = acc;
        }
        __syncthreads();

        if (edge && tid < 21) {
            float acc = sdb2s;
#pragma unroll
            for (int k = 0; k < KS; k++) {
                int idx; bool ok;
                if (left) { idx = tid + k - 7; ok = (idx >= 0); }
                else      { idx = tid + k;     ok = (idx < 28); }
                if (ok) {
                    float2 w = unpk2(sdw2p[k]);
                    acc += w.x * y1e[idx] + w.y * y1e[28 + idx];
                }
            }
            int tG = left ? tid : (T_LEN - 21 + tid);
            outp[(size_t)b * T_LEN + tG] = acc;
        }
    }
}

// ---------------------------------------------------------------------------
extern "C" void kernel_launch(void* const* d_in, const int* in_sizes, int n_in,
                              void* d_out, int out_size)
{
    const float* x   = (const float*)d_in[0];
    const float* W1  = (const float*)d_in[1];
    const float* b1  = (const float*)d_in[2];
    const float* W2  = (const float*)d_in[3];
    const float* b2  = (const float*)d_in[4];
    const float* fcW = (const float*)d_in[5];
    const float* fcb = (const float*)d_in[6];
    const float* dW0 = (const float*)d_in[7];
    const float* db0 = (const float*)d_in[8];
    const float* dW1 = (const float*)d_in[9];
    const float* db1 = (const float*)d_in[10];
    const float* dW2 = (const float*)d_in[11];
    const float* db2 = (const float*)d_in[12];

    float* out = (float*)d_out;
    float* outMain = out;                                        // (B, T)
    float* latent  = out + (size_t)B_SZ * T_LEN;                 // (B, E, T)
    float* sig     = latent + (size_t)B_SZ * E_CH * T_LEN;       // (B, E, T)
    float* pOut    = sig + (size_t)B_SZ * E_CH * T_LEN;          // (B, E, 1)
    float* fOut    = pOut + B_SZ * E_CH;
    float* aOut    = fOut + B_SZ * E_CH;
    float* bOut    = aOut + B_SZ * E_CH;

    const size_t smA = (size_t)8448 * sizeof(float) + (size_t)8704 * sizeof(ull);
    const size_t smB = (size_t)(4352 * 2 + 512) * sizeof(float2);
    const size_t smD = (size_t)(4 * (TD + 42)) * sizeof(float2)
                     + (size_t)(4 * (TD + 8) + 4 * 36 + 2 * 28) * sizeof(float);

    cudaFuncSetAttribute(latent_kernel,   cudaFuncAttributeMaxDynamicSharedMemorySize, (int)smA);
    cudaFuncSetAttribute(fft_kernel,      cudaFuncAttributeMaxDynamicSharedMemorySize, (int)smB);
    cudaFuncSetAttribute(sig_tree_kernel, cudaFuncAttributeMaxDynamicSharedMemorySize, (int)smD);

    latent_kernel<<<B_SZ * E_CH, 256, smA>>>(x, W1, b1, W2, b2, latent);
    fft_kernel<<<B_SZ * E_CH, 512, smB>>>(latent, fcW, fcb, pOut, fOut, aOut, bOut);
    sig_tree_kernel<<<B_SZ * (T_LEN / TD), 256, smD>>>(pOut, fOut, aOut, bOut,
                                                       dW0, db0, dW1, db1, dW2, db2,
                                                       sig, outMain);
}

// round 11
// speedup vs baseline: 1.4701x; 1.2028x over previous
#include <cuda_runtime.h>
#include <math_constants.h>

#define T_LEN 8192
#define B_SZ  256
#define E_CH  8
#define KS    15
#define TD    1024
#define TPI_F 6.28318530717958647692f

#define PAD(i)   ((i) + ((i) >> 5))
#define F2PAD(i) ((i) + ((i) >> 4))

typedef unsigned long long ull;

// ---- packed f32x2 helpers ----
__device__ __forceinline__ ull pk2(float lo, float hi) {
    ull r;
    asm("mov.b64 %0, {%1, %2};" : "=l"(r) : "f"(lo), "f"(hi));
    return r;
}
__device__ __forceinline__ float2 unpk2(ull v) {
    float lo, hi;
    asm("mov.b64 {%0, %1}, %2;" : "=f"(lo), "=f"(hi) : "l"(v));
    return make_float2(lo, hi);
}
__device__ __forceinline__ ull fma2(ull a, ull b, ull c) {
    ull d;
    asm("fma.rn.f32x2 %0, %1, %2, %3;" : "=l"(d) : "l"(a), "l"(b), "l"(c));
    return d;
}
__device__ __forceinline__ ull add2(ull a, ull b) {
    ull d;
    asm("add.rn.f32x2 %0, %1, %2;" : "=l"(d) : "l"(a), "l"(b));
    return d;
}

__device__ __forceinline__ float2 cmulf(float2 a, float2 b) {
    return make_float2(a.x * b.x - a.y * b.y, a.x * b.y + a.y * b.x);
}
__device__ __forceinline__ float2 cadd(float2 a, float2 b) {
    return make_float2(a.x + b.x, a.y + b.y);
}
__device__ __forceinline__ float2 csub(float2 a, float2 b) {
    return make_float2(a.x - b.x, a.y - b.y);
}

// compensated float-float accumulation (TwoSum based)
__device__ __forceinline__ float2 df_add(float2 a, float2 b) {
    float s = a.x + b.x;
    float v = s - a.x;
    float e = (a.x - (s - v)) + (b.x - v);
    e = e + a.y + b.y;
    float hi = s + e;
    return make_float2(hi, e - (hi - s));
}
__device__ __forceinline__ float2 df_addf(float2 a, float b) {
    return df_add(a, make_float2(b, 0.f));
}

// ---------------------------------------------------------------------------
// Kernel A: fused per-channel dilated conv pair -> latent (B,E,T)
// Coset-blocked register streaming + packed f32x2 math. (R5 proven body.)
// ---------------------------------------------------------------------------
__global__ __launch_bounds__(256, 2) void latent_kernel(
    const float* __restrict__ x,
    const float* __restrict__ W1, const float* __restrict__ b1,
    const float* __restrict__ W2, const float* __restrict__ b2,
    float* __restrict__ latent)
{
    extern __shared__ float sm[];
    float* sx  = sm;                               // PAD(8192) -> 8448 floats
    ull*   shp = (ull*)(sm + 8448);                // F2PAD(8192) -> 8704 ull

    const int be = blockIdx.x;
    const int e  = be & 7;
    const int b  = be >> 3;
    const int d  = 1 << e;
    const int tid = threadIdx.x;

    const float* xrow = x + (size_t)b * T_LEN;
    for (int i = tid; i < T_LEN; i += 256) sx[PAD(i)] = xrow[i];

    ull w1pk[KS];
#pragma unroll
    for (int j = 0; j < KS; j++)
        w1pk[j] = pk2(W1[e * 30 + j], W1[e * 30 + 15 + j]);
    const ull bias1 = pk2(b1[2 * e], b1[2 * e + 1]);
    __syncthreads();

#pragma unroll 1
    for (int it = 0; it < 4; it++) {
        const int cc = it * 256 + tid;
        const int p  = cc & (d - 1);
        const int qc = cc >> e;
        const int tb = p + (qc << (e + 3));
        ull xd[22];
#pragma unroll
        for (int m = 0; m < 22; m++) {
            int idx = tb + (m - 7) * d;
            float v = ((unsigned)idx < (unsigned)T_LEN) ? sx[PAD(idx)] : 0.f;
            xd[m] = pk2(v, v);
        }
#pragma unroll
        for (int rr = 0; rr < 8; rr++) {
            ull a0 = bias1, a1 = 0ULL;
#pragma unroll
            for (int j = 0; j < KS; j += 2) a0 = fma2(w1pk[j], xd[rr + j], a0);
#pragma unroll
            for (int j = 1; j < KS; j += 2) a1 = fma2(w1pk[j], xd[rr + j], a1);
            shp[F2PAD(tb + rr * d)] = add2(a0, a1);
        }
    }

    ull w2pk[KS];
#pragma unroll
    for (int k = 0; k < KS; k++)
        w2pk[k] = pk2(W2[e * 30 + k], W2[e * 30 + 15 + k]);
    const ull bias2 = pk2(b2[e], 0.f);
    __syncthreads();

#pragma unroll 1
    for (int it = 0; it < 4; it++) {
        const int cc = it * 256 + tid;
        const int p  = cc & (d - 1);
        const int qc = cc >> e;
        const int tb = p + (qc << (e + 3));
        ull gp[22];
#pragma unroll
        for (int m = 0; m < 22; m++) {
            int idx = tb + (m - 7) * d;
            gp[m] = ((unsigned)idx < (unsigned)T_LEN) ? shp[F2PAD(idx)] : 0ULL;
        }
#pragma unroll
        for (int rr = 0; rr < 8; rr++) {
            ull a0 = bias2, a1 = 0ULL;
#pragma unroll
            for (int k = 0; k < KS; k += 2) a0 = fma2(w2pk[k], gp[rr + k], a0);
#pragma unroll
            for (int k = 1; k < KS; k += 2) a1 = fma2(w2pk[k], gp[rr + k], a1);
            float2 r = unpk2(add2(a0, a1));
            sx[PAD(tb + rr * d)] = r.x + r.y;
        }
    }
    __syncthreads();

    float* lrow = latent + (size_t)be * T_LEN;
    for (int i = tid; i < T_LEN; i += 256) lrow[i] = sx[PAD(i)];
}

// ---------------------------------------------------------------------------
// Kernel B: per-(b,e) row — fc dots, real FFT (8192 real via complex 4096),
// radix-8 Stockham, stage-0 fused with load, stage-3 outputs in registers.
// Slimmed reductions: plain fp32 per-thread partials + pairwise shuffle tree
// (compensation kept only on the cancellation-prone fc dots).
// ---------------------------------------------------------------------------
__global__ __launch_bounds__(512, 2) void fft_kernel(
    const float* __restrict__ latent,
    const float* __restrict__ fcW, const float* __restrict__ fcb,
    float* __restrict__ pOut, float* __restrict__ fOut,
    float* __restrict__ aOut, float* __restrict__ bOut)
{
    const int M = 4096;
    extern __shared__ float smf[];
    float2* bufA = (float2*)smf;         // F2PAD -> 4352 slots
    float2* bufB = bufA + 4352;
    float2* tw   = bufB + 4352;          // 512 twiddles
    __shared__ float red[64];

    const int be = blockIdx.x;
    const int e  = be & 7;
    const int tid = threadIdx.x;
    const float RS = 0.70710678118654752440f;

    const float2* rowc = (const float2*)(latent + (size_t)be * T_LEN);
    const float2* fw0  = (const float2*)(fcW + (size_t)(e * 2 + 0) * T_LEN);
    const float2* fw1  = (const float2*)(fcW + (size_t)(e * 2 + 1) * T_LEN);

    // ---- fused: global load + fc dots (compensated) + stage 0 ----
    float2 v0 = make_float2(0.f, 0.f), v1 = make_float2(0.f, 0.f);
    float2 z[8];
#pragma unroll
    for (int q = 0; q < 8; q++) {
        const int i = tid + 512 * q;
        float2 zz = rowc[i];
        z[q] = zz;
        float2 a0 = fw0[i], a1 = fw1[i];
        v0 = df_addf(v0, zz.x * a0.x + zz.y * a0.y);
        v1 = df_addf(v1, zz.x * a1.x + zz.y * a1.y);
    }
    {
        float s, c;
        sincosf(-(float)CUDART_PI * (float)tid / 2048.0f, &s, &c);
        tw[tid] = make_float2(c, s);
    }
    {
        float2 t0 = cadd(z[0], z[4]), t1 = csub(z[0], z[4]);
        float2 t2 = cadd(z[2], z[6]), t3 = csub(z[2], z[6]);
        float2 E0 = cadd(t0, t2);
        float2 E1 = make_float2(t1.x + t3.y, t1.y - t3.x);
        float2 E2 = csub(t0, t2);
        float2 E3 = make_float2(t1.x - t3.y, t1.y + t3.x);
        float2 s0 = cadd(z[1], z[5]), s1 = csub(z[1], z[5]);
        float2 s2 = cadd(z[3], z[7]), s3 = csub(z[3], z[7]);
        float2 O0 = cadd(s0, s2);
        float2 O1 = make_float2(s1.x + s3.y, s1.y - s3.x);
        float2 O2 = csub(s0, s2);
        float2 O3 = make_float2(s1.x - s3.y, s1.y + s3.x);
        float2 Q1 = make_float2(RS * (O1.x + O1.y), RS * (O1.y - O1.x));
        float2 Q2 = make_float2(O2.y, -O2.x);
        float2 Q3 = make_float2(RS * (O3.y - O3.x), -RS * (O3.x + O3.y));
        const int ob = tid << 3;
        bufA[F2PAD(ob)]     = cadd(E0, O0);
        bufA[F2PAD(ob + 1)] = cadd(E1, Q1);
        bufA[F2PAD(ob + 2)] = cadd(E2, Q2);
        bufA[F2PAD(ob + 3)] = cadd(E3, Q3);
        bufA[F2PAD(ob + 4)] = csub(E0, O0);
        bufA[F2PAD(ob + 5)] = csub(E1, Q1);
        bufA[F2PAD(ob + 6)] = csub(E2, Q2);
        bufA[F2PAD(ob + 7)] = csub(E3, Q3);
    }
    __syncthreads();

    // ---- stages 1,2 ----
    float2* bin  = bufA;
    float2* bout = bufB;
#pragma unroll
    for (int sg = 1; sg <= 2; sg++) {
        const int m = 1 << (3 * sg);
        const int idx = tid;
        const int r = idx & (m - 1);
        float2 W = tw[r << (9 - 3 * sg)];

        float2 u0 = bin[F2PAD(idx)];
        float2 z1 = bin[F2PAD(idx + 512)];
        float2 z2 = bin[F2PAD(idx + 1024)];
        float2 z3 = bin[F2PAD(idx + 1536)];
        float2 z4 = bin[F2PAD(idx + 2048)];
        float2 z5 = bin[F2PAD(idx + 2560)];
        float2 z6 = bin[F2PAD(idx + 3072)];
        float2 z7 = bin[F2PAD(idx + 3584)];

        float2 W2 = cmulf(W, W);
        float2 W3 = cmulf(W2, W);
        float2 W4 = cmulf(W2, W2);
        float2 W5 = cmulf(W4, W);
        float2 W6 = cmulf(W4, W2);
        float2 W7 = cmulf(W4, W3);

        float2 u1 = cmulf(z1, W);
        float2 u2 = cmulf(z2, W2);
        float2 u3 = cmulf(z3, W3);
        float2 u4 = cmulf(z4, W4);
        float2 u5 = cmulf(z5, W5);
        float2 u6 = cmulf(z6, W6);
        float2 u7 = cmulf(z7, W7);

        float2 t0 = cadd(u0, u4), t1 = csub(u0, u4);
        float2 t2 = cadd(u2, u6), t3 = csub(u2, u6);
        float2 E0 = cadd(t0, t2);
        float2 E1 = make_float2(t1.x + t3.y, t1.y - t3.x);
        float2 E2 = csub(t0, t2);
        float2 E3 = make_float2(t1.x - t3.y, t1.y + t3.x);
        float2 s0 = cadd(u1, u5), s1 = csub(u1, u5);
        float2 s2 = cadd(u3, u7), s3 = csub(u3, u7);
        float2 O0 = cadd(s0, s2);
        float2 O1 = make_float2(s1.x + s3.y, s1.y - s3.x);
        float2 O2 = csub(s0, s2);
        float2 O3 = make_float2(s1.x - s3.y, s1.y + s3.x);
        float2 Q1 = make_float2(RS * (O1.x + O1.y), RS * (O1.y - O1.x));
        float2 Q2 = make_float2(O2.y, -O2.x);
        float2 Q3 = make_float2(RS * (O3.y - O3.x), -RS * (O3.x + O3.y));

        const int ob = ((idx - r) << 3) + r;
        bout[F2PAD(ob)]         = cadd(E0, O0);
        bout[F2PAD(ob + m)]     = cadd(E1, Q1);
        bout[F2PAD(ob + 2 * m)] = cadd(E2, Q2);
        bout[F2PAD(ob + 3 * m)] = cadd(E3, Q3);
        bout[F2PAD(ob + 4 * m)] = csub(E0, O0);
        bout[F2PAD(ob + 5 * m)] = csub(E1, Q1);
        bout[F2PAD(ob + 6 * m)] = csub(E2, Q2);
        bout[F2PAD(ob + 7 * m)] = csub(E3, Q3);
        __syncthreads();
        float2* tmp = bin; bin = bout; bout = tmp;
    }

    // ---- stage 3 (last): natural-order outputs kept in registers ----
    {
        const int idx = tid;
        float2 W = tw[idx];

        float2 u0 = bin[F2PAD(idx)];
        float2 z1 = bin[F2PAD(idx + 512)];
        float2 z2 = bin[F2PAD(idx + 1024)];
        float2 z3 = bin[F2PAD(idx + 1536)];
        float2 z4 = bin[F2PAD(idx + 2048)];
        float2 z5 = bin[F2PAD(idx + 2560)];
        float2 z6 = bin[F2PAD(idx + 3072)];
        float2 z7 = bin[F2PAD(idx + 3584)];

        float2 W2 = cmulf(W, W);
        float2 W3 = cmulf(W2, W);
        float2 W4 = cmulf(W2, W2);
        float2 W5 = cmulf(W4, W);
        float2 W6 = cmulf(W4, W2);
        float2 W7 = cmulf(W4, W3);

        float2 u1 = cmulf(z1, W);
        float2 u2 = cmulf(z2, W2);
        float2 u3 = cmulf(z3, W3);
        float2 u4 = cmulf(z4, W4);
        float2 u5 = cmulf(z5, W5);
        float2 u6 = cmulf(z6, W6);
        float2 u7 = cmulf(z7, W7);

        float2 t0 = cadd(u0, u4), t1 = csub(u0, u4);
        float2 t2 = cadd(u2, u6), t3 = csub(u2, u6);
        float2 E0 = cadd(t0, t2);
        float2 E1 = make_float2(t1.x + t3.y, t1.y - t3.x);
        float2 E2 = csub(t0, t2);
        float2 E3 = make_float2(t1.x - t3.y, t1.y + t3.x);
        float2 s0 = cadd(u1, u5), s1 = csub(u1, u5);
        float2 s2 = cadd(u3, u7), s3 = csub(u3, u7);
        float2 O0 = cadd(s0, s2);
        float2 O1 = make_float2(s1.x + s3.y, s1.y - s3.x);
        float2 O2 = csub(s0, s2);
        float2 O3 = make_float2(s1.x - s3.y, s1.y + s3.x);
        float2 Q1 = make_float2(RS * (O1.x + O1.y), RS * (O1.y - O1.x));
        float2 Q2 = make_float2(O2.y, -O2.x);
        float2 Q3 = make_float2(RS * (O3.y - O3.x), -RS * (O3.x + O3.y));

        z[0] = cadd(E0, O0); z[1] = cadd(E1, Q1);
        z[2] = cadd(E2, Q2); z[3] = cadd(E3, Q3);
        z[4] = csub(E0, O0); z[5] = csub(E1, Q1);
        z[6] = csub(E2, Q2); z[7] = csub(E3, Q3);
#pragma unroll
        for (int q = 0; q < 8; q++)
            bout[F2PAD(idx + 512 * q)] = z[q];
    }
    __syncthreads();
    // bout holds Z_k natural order; thread tid holds z[q] = Z_{tid+512q}

    // ---- reduction: plain fp32 partials (8-16 terms each), pairwise tree ----
    float psum = 0.f, wsum = 0.f;
#pragma unroll
    for (int q = 0; q < 8; q++) {
        const int k = tid + 512 * q;
        if (k > 0) {
            float2 zk = z[q];
            float2 zm = bout[F2PAD(M - k)];
            float Ax = 0.5f * (zk.x + zm.x), Ay = 0.5f * (zk.y - zm.y);
            float Bx = 0.5f * (zk.x - zm.x), By = 0.5f * (zk.y + zm.y);
            float s, c;
            __sincosf(-(float)CUDART_PI * (float)k / (float)M, &s, &c);
            float Xr = Ax + c * By + s * Bx;
            float Xi = Ay - c * Bx + s * By;
            float pw = Xr * Xr + Xi * Xi;
            psum += pw;
            wsum = fmaf((float)k, pw, wsum);
        }
    }
    if (tid == 0) {
        float xm = z[0].x - z[0].y;       // Nyquist (real)
        psum += xm * xm;
        wsum = fmaf((float)M, xm * xm, wsum);
    }

    float v0s = v0.x + v0.y;
    float v1s = v1.x + v1.y;

    const unsigned mask = 0xffffffffu;
#pragma unroll
    for (int o = 16; o > 0; o >>= 1) {
        psum += __shfl_down_sync(mask, psum, o);
        wsum += __shfl_down_sync(mask, wsum, o);
        v0s  += __shfl_down_sync(mask, v0s, o);
        v1s  += __shfl_down_sync(mask, v1s, o);
    }
    const int warp = tid >> 5, lane = tid & 31;
    if (lane == 0) {
        red[warp] = psum; red[16 + warp] = wsum;
        red[32 + warp] = v0s; red[48 + warp] = v1s;
    }
    __syncthreads();
    if (tid == 0) {
        double P = 0, Wm = 0, V0 = 0, V1 = 0;
        for (int i = 0; i < 16; i++) {
            P  += (double)red[i];
            Wm += (double)red[16 + i];
            V0 += (double)red[32 + i];
            V1 += (double)red[48 + i];
        }
        V0 += (double)fcb[e * 2];
        V1 += (double)fcb[e * 2 + 1];
        float f    = (float)(0.5 * Wm / P);
        float a    = 2.0f * sqrtf((float)P) / (float)T_LEN;
        float boff = (z[0].x + z[0].y) / (float)T_LEN;   // Z_0 in regs
        float p    = atan2f((float)V1, (float)V0) / TPI_F;
        pOut[be] = p; fOut[be] = f; aOut[be] = a; bOut[be] = boff;
    }
}

// ---------------------------------------------------------------------------
// Kernel D: sinusoid resynthesis + ANALYTIC deconv tree. (R9 proven version.)
// ---------------------------------------------------------------------------
__global__ __launch_bounds__(256) void sig_tree_kernel(
    const float* __restrict__ pArr, const float* __restrict__ fArr,
    const float* __restrict__ aArr, const float* __restrict__ bArr,
    const float* __restrict__ dW0, const float* __restrict__ db0,
    const float* __restrict__ dW1, const float* __restrict__ db1,
    const float* __restrict__ dW2, const float* __restrict__ db2,
    float* __restrict__ sig, float* __restrict__ outp)
{
    extern __shared__ float smd[];
    const int SW  = TD + 42;     // 1066 sig slots per pair-row (halo 21)
    const int SPW = TD + 8;      // padded spart row
    float2* ssig2 = (float2*)smd;                 // 4 * SW float2
    float*  spart = (float*)(ssig2 + 4 * SW);     // 4 * SPW floats
    float*  y0e   = spart + 4 * SPW;              // 4 * 36
    float*  y1e   = y0e + 4 * 36;                 // 2 * 28

    __shared__ float sca[8], scf[8], scp[8], scb[8];
    __shared__ float2 rotv[8];
    __shared__ float sGr[8], sGi[8];
    __shared__ float sC;
    __shared__ ull sdw0p[4 * KS], sdw1p[2 * KS], sdw2p[KS];
    __shared__ float sdb0[4], sdb1[2], sdb2s;

    const int blk  = blockIdx.x;
    const int tile = blk & 7;
    const int b    = blk >> 3;
    const int t0   = tile * TD;
    const int tid  = threadIdx.x;
    const float inv = 2.0f / (float)(T_LEN - 1);

    if (tid < 8) {
        const int e = tid;
        float fv = fArr[b * 8 + e];
        float av = aArr[b * 8 + e];
        sca[e] = av; scf[e] = fv;
        scp[e] = pArr[b * 8 + e]; scb[e] = bArr[b * 8 + e];
        float S, C;
        sincospif(2.0f * fv * inv, &S, &C);
        rotv[e] = make_float2(C, S);

        float h0r = 0.f, h0i = 0.f, h1r = 0.f, h1i = 0.f, h2r = 0.f, h2i = 0.f;
        const int row1 = ((e >> 2) << 1) | ((e >> 1) & 1);
        const int row2 = e >> 2;
#pragma unroll
        for (int k = 0; k < KS; k++) {
            float ph = 2.0f * fv * (float)(k - 7) * inv;
            float ss, cc;
            sincospif(ph, &ss, &cc);
            float w0 = dW0[e * KS + k];
            float w1 = dW1[row1 * KS + k];
            float w2 = dW2[row2 * KS + k];
            h0r += w0 * cc; h0i += w0 * ss;
            h1r += w1 * cc; h1i += w1 * ss;
            h2r += w2 * cc; h2i += w2 * ss;
        }
        float g1r = h0r * h1r - h0i * h1i;
        float g1i = h0r * h1i + h0i * h1r;
        sGr[e] = av * (g1r * h2r - g1i * h2i);
        sGi[e] = av * (g1r * h2i + g1i * h2r);
    }
    if (tid == 8) {
        float S0[8], S1[4], S2[2];
        for (int e2 = 0; e2 < 8; e2++) {
            float s = 0.f;
            for (int k = 0; k < KS; k++) s += dW0[e2 * KS + k];
            S0[e2] = s;
        }
        for (int g = 0; g < 4; g++) {
            float s = 0.f;
            for (int k = 0; k < KS; k++) s += dW1[g * KS + k];
            S1[g] = s;
        }
        for (int q = 0; q < 2; q++) {
            float s = 0.f;
            for (int k = 0; k < KS; k++) s += dW2[q * KS + k];
            S2[q] = s;
        }
        float Cv = db2[0];
        for (int q = 0; q < 2; q++) Cv += S2[q] * db1[q];
        for (int g = 0; g < 4; g++) Cv += S2[g >> 1] * S1[g] * db0[g];
        for (int e2 = 0; e2 < 8; e2++)
            Cv += S2[e2 >> 2] * S1[e2 >> 1] * S0[e2] * bArr[b * 8 + e2];
        sC = Cv;
    }
    if (tid < 4 * KS) {
        int g = tid / KS, k = tid - g * KS;
        sdw0p[tid] = pk2(dW0[(2 * g) * KS + k], dW0[(2 * g + 1) * KS + k]);
    }
    if (tid < 2 * KS) {
        int g = tid / KS, k = tid - g * KS;
        sdw1p[tid] = pk2(dW1[(2 * g) * KS + k], dW1[(2 * g + 1) * KS + k]);
    }
    if (tid < KS) sdw2p[tid] = pk2(dW2[tid], dW2[KS + tid]);
    if (tid < 4) sdb0[tid] = db0[tid];
    if (tid < 2) sdb1[tid] = db1[tid];
    if (tid == 0) sdb2s = db2[0];
    __syncthreads();

    {
        const int pr  = tid >> 6;
        const int sub = tid & 63;
        const int j0  = sub * 17;
        const int ts  = t0 - 21 + j0;
        const int e0 = 2 * pr, e1 = 2 * pr + 1;
        const float arg0 = -1.0f + (float)ts * inv;
        float s0, c0, s1, c1;
        sincospif(2.0f * (scf[e0] * arg0 + scp[e0]), &s0, &c0);
        sincospif(2.0f * (scf[e1] * arg0 + scp[e1]), &s1, &c1);
        const float2 r0 = rotv[e0], r1 = rotv[e1];
        const float a0 = sca[e0], b0 = scb[e0];
        const float a1 = sca[e1], b1v = scb[e1];
        const float gr0 = sGr[e0], gi0 = sGi[e0];
        const float gr1 = sGr[e1], gi1 = sGi[e1];
        float* sprow = spart + pr * SPW;
#pragma unroll
        for (int jj = 0; jj < 17; jj++) {
            int j = j0 + jj;
            int t = ts + jj;
            if (j < SW) {
                bool ok = ((unsigned)t < (unsigned)T_LEN);
                float v0 = ok ? (a0 * s0 + b0)  : 0.f;
                float v1 = ok ? (a1 * s1 + b1v) : 0.f;
                ssig2[pr * SW + j] = make_float2(v0, v1);
                if (j >= 21 && j < 21 + TD)
                    sprow[j - 21] = gr0 * s0 + gi0 * c0 + gr1 * s1 + gi1 * c1;
            }
            float ns0 = s0 * r0.x + c0 * r0.y;
            c0 = c0 * r0.x - s0 * r0.y; s0 = ns0;
            float ns1 = s1 * r1.x + c1 * r1.y;
            c1 = c1 * r1.x - s1 * r1.y; s1 = ns1;
        }
    }
    __syncthreads();

    for (int i = tid; i < 8 * TD; i += 256) {
        int e = i >> 10, jj = i & (TD - 1);
        float2 v = ssig2[(e >> 1) * SW + 21 + jj];
        sig[((size_t)b * 8 + e) * T_LEN + t0 + jj] = (e & 1) ? v.y : v.x;
    }

    {
        const float Cv = sC;
        const bool left  = (tile == 0);
        const bool right = (tile == 7);
        float* orow = outp + (size_t)b * T_LEN + t0;
#pragma unroll
        for (int jj = tid; jj < TD; jj += 256) {
            bool skip = (left && jj < 21) || (right && jj >= TD - 21);
            if (!skip) {
                orow[jj] = spart[jj] + spart[SPW + jj] +
                           spart[2 * SPW + jj] + spart[3 * SPW + jj] + Cv;
            }
        }
    }

    {
        const bool left  = (tile == 0);
        const bool right = (tile == 7);
        const bool edge  = left || right;

        if (edge && tid < 140) {
            const int g = tid / 35, j = tid - g * 35;
            float acc = sdb0[g];
#pragma unroll
            for (int k = 0; k < KS; k++) {
                int tG = (left ? j : (T_LEN - 35 + j)) + k - 7;
                int slot = tG - t0 + 21;
                float2 w = unpk2(sdw0p[g * KS + k]);
                float2 sv = ssig2[g * SW + slot];
                acc += w.x * sv.x + w.y * sv.y;
            }
            y0e[g * 36 + j] = acc;
        }
        __syncthreads();

        if (edge && tid < 56) {
            const int g1 = tid / 28, j = tid - g1 * 28;
            float acc = sdb1[g1];
#pragma unroll
            for (int k = 0; k < KS; k++) {
                int idx; bool ok;
                if (left) { idx = j + k - 7; ok = (idx >= 0); }
                else      { idx = j + k;     ok = (idx < 35); }
                if (ok) {
                    float2 w = unpk2(sdw1p[g1 * KS + k]);
                    acc += w.x * y0e[(2 * g1) * 36 + idx]
                         + w.y * y0e[(2 * g1 + 1) * 36 + idx];
                }
            }
            y1e[g1 * 28 + j] = acc;
        }
        __syncthreads();

        if (edge && tid < 21) {
            float acc = sdb2s;
#pragma unroll
            for (int k = 0; k < KS; k++) {
                int idx; bool ok;
                if (left) { idx = tid + k - 7; ok = (idx >= 0); }
                else      { idx = tid + k;     ok = (idx < 28); }
                if (ok) {
                    float2 w = unpk2(sdw2p[k]);
                    acc += w.x * y1e[idx] + w.y * y1e[28 + idx];
                }
            }
            int tG = left ? tid : (T_LEN - 21 + tid);
            outp[(size_t)b * T_LEN + tG] = acc;
        }
    }
}

// ---------------------------------------------------------------------------
extern "C" void kernel_launch(void* const* d_in, const int* in_sizes, int n_in,
                              void* d_out, int out_size)
{
    const float* x   = (const float*)d_in[0];
    const float* W1  = (const float*)d_in[1];
    const float* b1  = (const float*)d_in[2];
    const float* W2  = (const float*)d_in[3];
    const float* b2  = (const float*)d_in[4];
    const float* fcW = (const float*)d_in[5];
    const float* fcb = (const float*)d_in[6];
    const float* dW0 = (const float*)d_in[7];
    const float* db0 = (const float*)d_in[8];
    const float* dW1 = (const float*)d_in[9];
    const float* db1 = (const float*)d_in[10];
    const float* dW2 = (const float*)d_in[11];
    const float* db2 = (const float*)d_in[12];

    float* out = (float*)d_out;
    float* outMain = out;                                        // (B, T)
    float* latent  = out + (size_t)B_SZ * T_LEN;                 // (B, E, T)
    float* sig     = latent + (size_t)B_SZ * E_CH * T_LEN;       // (B, E, T)
    float* pOut    = sig + (size_t)B_SZ * E_CH * T_LEN;          // (B, E, 1)
    float* fOut    = pOut + B_SZ * E_CH;
    float* aOut    = fOut + B_SZ * E_CH;
    float* bOut    = aOut + B_SZ * E_CH;

    const size_t smA = (size_t)8448 * sizeof(float) + (size_t)8704 * sizeof(ull);
    const size_t smB = (size_t)(4352 * 2 + 512) * sizeof(float2);
    const size_t smD = (size_t)(4 * (TD + 42)) * sizeof(float2)
                     + (size_t)(4 * (TD + 8) + 4 * 36 + 2 * 28) * sizeof(float);

    cudaFuncSetAttribute(latent_kernel,   cudaFuncAttributeMaxDynamicSharedMemorySize, (int)smA);
    cudaFuncSetAttribute(fft_kernel,      cudaFuncAttributeMaxDynamicSharedMemorySize, (int)smB);
    cudaFuncSetAttribute(sig_tree_kernel, cudaFuncAttributeMaxDynamicSharedMemorySize, (int)smD);

    latent_kernel<<<B_SZ * E_CH, 256, smA>>>(x, W1, b1, W2, b2, latent);
    fft_kernel<<<B_SZ * E_CH, 512, smB>>>(latent, fcW, fcb, pOut, fOut, aOut, bOut);
    sig_tree_kernel<<<B_SZ * (T_LEN / TD), 256, smD>>>(pOut, fOut, aOut, bOut,
                                                       dW0, db0, dW1, db1, dW2, db2,
                                                       sig, outMain);
}